// round 12
// baseline (speedup 1.0000x reference)
#include <cuda_runtime.h>
#include <math_constants.h>
#include <cstdint>

#define RR 32
#define R3 32768
#define C 240
#define C2 480
#define NB 4
#define NP 32768
#define NVOX (NB * R3)
#define NOCCMAX 131072
#define BN_EPS 1e-5f

// ---------------- static scratch ----------------
__device__ float    g_cpart[128][3];
__device__ float    g_meanv[NB][3];
__device__ unsigned g_qmax[NB];
__device__ int   g_pos[NB * NP];
__device__ int   g_count[NVOX];
__device__ int   g_offset[NVOX];
__device__ int   g_gidx[NVOX];          // compact index per voxel (per batch), -1 if empty
__device__ int   g_boc[NB];             // occupied count per batch
__device__ int   g_plist[NB * NP];
__device__ float g_ft[(size_t)NB * NP * C];     // features transposed [B][N][C]
__device__ float g_fea[(size_t)NVOX * C2];      // COMPACT (padded) voxel features [slot][2C]
__device__ float g_yc[(size_t)C * NOCCMAX];     // COMPACT gemm output [c][slot] (incl bias)
__device__ float g_wr[256 * C2];
__device__ float g_sum[C];
__device__ float g_sum2[C];

// padded per-batch start: sum over j<b of ceil(boc[j]/128)*128
__device__ __forceinline__ int padded_start(int b) {
    int pb = 0;
    #pragma unroll
    for (int j = 0; j < NB; j++)
        if (j < b) pb += (g_boc[j] + 127) & ~127;
    return pb;
}

// ---------------- helpers ----------------
__device__ __forceinline__ float tf32_rna(float x) {
    uint32_t u; asm("cvt.rna.tf32.f32 %0, %1;" : "=r"(u) : "f"(x));
    return __uint_as_float(u);
}
__device__ __forceinline__ uint32_t smem_u32(const void* p) {
    uint32_t a;
    asm("{ .reg .u64 t; cvta.to.shared.u64 t, %1; cvt.u32.u64 %0, t; }" : "=r"(a) : "l"(p));
    return a;
}
__device__ __forceinline__ void cp_async16(uint32_t dst, const void* src) {
    asm volatile("cp.async.cg.shared.global [%0], [%1], 16;" :: "r"(dst), "l"(src) : "memory");
}
__device__ __forceinline__ void ldsm_x4(uint32_t* r, uint32_t addr) {
    asm volatile("ldmatrix.sync.aligned.m8n8.x4.shared.b16 {%0,%1,%2,%3}, [%4];"
                 : "=r"(r[0]), "=r"(r[1]), "=r"(r[2]), "=r"(r[3]) : "r"(addr));
}
__device__ __forceinline__ void mma_tf32(float* c, const uint32_t* a, uint32_t b0, uint32_t b1) {
    asm volatile("mma.sync.aligned.m16n8k8.row.col.f32.tf32.tf32.f32 "
                 "{%0,%1,%2,%3}, {%4,%5,%6,%7}, {%8,%9}, {%0,%1,%2,%3};"
                 : "+f"(c[0]), "+f"(c[1]), "+f"(c[2]), "+f"(c[3])
                 : "r"(a[0]), "r"(a[1]), "r"(a[2]), "r"(a[3]), "r"(b0), "r"(b1));
}

// ---------------- K_setup ----------------
__global__ void __launch_bounds__(256) k_setup(const float* __restrict__ w,
                                               const float* __restrict__ coords) {
    int i = blockIdx.x * 256 + threadIdx.x;
    if (i < NVOX) g_count[i] = 0;
    if (i < C) { g_sum[i] = 0.f; g_sum2[i] = 0.f; }
    if (i < NB) g_qmax[i] = 0u;
    if (i < 256 * C2) {
        int r = i / C2;
        g_wr[i] = (r < C) ? tf32_rna(w[i]) : 0.f;
    }
    if (blockIdx.x < 128) {
        int b = blockIdx.x >> 5;
        int idx = (blockIdx.x & 31) * 256 + threadIdx.x;
        const float4* cx = (const float4*)(coords + (size_t)b * 3 * NP);
        float4 a = cx[idx];
        float4 c = cx[NP / 4 + idx];
        float4 d = cx[NP / 2 + idx];
        float sx = (a.x + a.y) + (a.z + a.w);
        float sy = (c.x + c.y) + (c.z + c.w);
        float sz = (d.x + d.y) + (d.z + d.w);
        __shared__ float sh[3][8];
        int lane = threadIdx.x & 31, warp = threadIdx.x >> 5;
        #pragma unroll
        for (int o = 16; o; o >>= 1) {
            sx += __shfl_down_sync(0xffffffffu, sx, o);
            sy += __shfl_down_sync(0xffffffffu, sy, o);
            sz += __shfl_down_sync(0xffffffffu, sz, o);
        }
        if (lane == 0) { sh[0][warp] = sx; sh[1][warp] = sy; sh[2][warp] = sz; }
        __syncthreads();
        if (threadIdx.x == 0) {
            float tx = 0.f, ty = 0.f, tz = 0.f;
            #pragma unroll
            for (int j = 0; j < 8; j++) { tx += sh[0][j]; ty += sh[1][j]; tz += sh[2][j]; }
            g_cpart[blockIdx.x][0] = tx;
            g_cpart[blockIdx.x][1] = ty;
            g_cpart[blockIdx.x][2] = tz;
        }
    }
}

// ---------------- K_cmax ----------------
__global__ void __launch_bounds__(256) k_cmax(const float* __restrict__ coords) {
    int b = blockIdx.y;
    __shared__ float mean_s[3];
    if (threadIdx.x < 3) {
        float s = 0.f;
        #pragma unroll
        for (int j = 0; j < 32; j++) s += g_cpart[(b << 5) + j][threadIdx.x];
        float m = s * (1.0f / (float)NP);
        mean_s[threadIdx.x] = m;
        if (blockIdx.x == 0) g_meanv[b][threadIdx.x] = m;
    }
    __syncthreads();
    float m0 = mean_s[0], m1 = mean_s[1], m2 = mean_s[2];
    int idx = blockIdx.x * blockDim.x + threadIdx.x;
    const float4* cx = (const float4*)(coords + (size_t)b * 3 * NP);
    float4 a = cx[idx];
    float4 c = cx[NP / 4 + idx];
    float4 d = cx[NP / 2 + idx];
    float mx = 0.f, dx, dy, dz, q;
    dx = a.x - m0; dy = c.x - m1; dz = d.x - m2; q = dx*dx + dy*dy + dz*dz; mx = fmaxf(mx, q);
    dx = a.y - m0; dy = c.y - m1; dz = d.y - m2; q = dx*dx + dy*dy + dz*dz; mx = fmaxf(mx, q);
    dx = a.z - m0; dy = c.z - m1; dz = d.z - m2; q = dx*dx + dy*dy + dz*dz; mx = fmaxf(mx, q);
    dx = a.w - m0; dy = c.w - m1; dz = d.w - m2; q = dx*dx + dy*dy + dz*dz; mx = fmaxf(mx, q);
    __shared__ float sh[8];
    int lane = threadIdx.x & 31, warp = threadIdx.x >> 5;
    #pragma unroll
    for (int o = 16; o; o >>= 1) mx = fmaxf(mx, __shfl_down_sync(0xffffffffu, mx, o));
    if (lane == 0) sh[warp] = mx;
    __syncthreads();
    if (threadIdx.x == 0) {
        float t = 0.f;
        #pragma unroll
        for (int j = 0; j < 8; j++) t = fmaxf(t, sh[j]);
        atomicMax(&g_qmax[b], __float_as_uint(t));
    }
}

// ---------------- K2: nc + voxel id + count ----------------
__global__ void __launch_bounds__(256) k_voxelize(const float* __restrict__ coords,
                                                  float* __restrict__ nc_out, int write_nc) {
    int i = blockIdx.x * blockDim.x + threadIdx.x;
    if (i >= NB * NP) return;
    int b = i >> 15, n = i & (NP - 1);
    const float* base = coords + (size_t)b * 3 * NP;
    float sc = sqrtf(__uint_as_float(g_qmax[b])) * 2.0f;
    int vx[3];
    #pragma unroll
    for (int ch = 0; ch < 3; ch++) {
        float x = base[ch * NP + n];
        float u = (x - g_meanv[b][ch]) / sc + 0.5f;
        float t = fminf(fmaxf(u * (float)RR, 0.0f), (float)(RR - 1));
        if (write_nc) nc_out[((size_t)b * 3 + ch) * NP + n] = t;
        vx[ch] = (int)rintf(t);
    }
    int pos = vx[0] + vx[1] * RR + vx[2] * RR * RR;
    g_pos[i] = pos;
    atomicAdd(&g_count[(b << 15) + pos], 1);
}

// ---------------- K3: per-batch dual scan (points + occupancy) ----------------
__global__ void __launch_bounds__(1024) k_scan() {
    int b = blockIdx.x;
    int t = threadIdx.x;
    int base = b * R3 + t * 32;
    int4 v[8];
    const int4* src = (const int4*)(g_count + base);
    #pragma unroll
    for (int j = 0; j < 8; j++) v[j] = src[j];
    unsigned comb = 0;
    #pragma unroll
    for (int j = 0; j < 8; j++) {
        comb += ((unsigned)(v[j].x) << 16) + (v[j].x > 0);
        comb += ((unsigned)(v[j].y) << 16) + (v[j].y > 0);
        comb += ((unsigned)(v[j].z) << 16) + (v[j].z > 0);
        comb += ((unsigned)(v[j].w) << 16) + (v[j].w > 0);
    }
    __shared__ unsigned warp_sums[32];
    int lane = t & 31, warp = t >> 5;
    unsigned inc = comb;
    #pragma unroll
    for (int o = 1; o < 32; o <<= 1) {
        unsigned u = __shfl_up_sync(0xffffffffu, inc, o);
        if (lane >= o) inc += u;
    }
    if (lane == 31) warp_sums[warp] = inc;
    __syncthreads();
    if (warp == 0) {
        unsigned w = warp_sums[lane];
        #pragma unroll
        for (int o = 1; o < 32; o <<= 1) {
            unsigned u = __shfl_up_sync(0xffffffffu, w, o);
            if (lane >= o) w += u;
        }
        warp_sums[lane] = w;
    }
    __syncthreads();
    unsigned excl = inc - comb + (warp ? warp_sums[warp - 1] : 0u);
    int run_pts = (int)(excl >> 16);
    int run_occ = (int)(excl & 0xFFFFu);
    int4* dsto = (int4*)(g_offset + base);
    int4* dstg = (int4*)(g_gidx + base);
    #pragma unroll
    for (int j = 0; j < 8; j++) {
        int4 o, g;
        o.x = run_pts; g.x = (v[j].x > 0) ? run_occ : -1; run_pts += v[j].x; run_occ += (v[j].x > 0);
        o.y = run_pts; g.y = (v[j].y > 0) ? run_occ : -1; run_pts += v[j].y; run_occ += (v[j].y > 0);
        o.z = run_pts; g.z = (v[j].z > 0) ? run_occ : -1; run_pts += v[j].z; run_occ += (v[j].z > 0);
        o.w = run_pts; g.w = (v[j].w > 0) ? run_occ : -1; run_pts += v[j].w; run_occ += (v[j].w > 0);
        dsto[j] = o;
        dstg[j] = g;
    }
    if (t == 1023) g_boc[b] = run_occ;
}

// ---------------- K4: scatter ----------------
__global__ void __launch_bounds__(256) k_scatter() {
    int i = blockIdx.x * blockDim.x + threadIdx.x;
    if (i >= NB * NP) return;
    int b = i >> 15, n = i & (NP - 1);
    int pos = g_pos[i];
    int slot = atomicAdd(&g_offset[(b << 15) + pos], 1);
    g_plist[(b << 15) + slot] = n;
}

// ---------------- K5: transpose (per batch, side stream) ----------------
__global__ void __launch_bounds__(256) k_transpose(const float* __restrict__ f, int b) {
    __shared__ float tile[32][33];
    int n0 = blockIdx.x * 32, c0 = blockIdx.y * 32;
    int n = n0 + threadIdx.x;
    for (int j = threadIdx.y; j < 32; j += 8) {
        int c = c0 + j;
        tile[j][threadIdx.x] = (c < C) ? f[((size_t)b * C + c) * NP + n] : 0.f;
    }
    __syncthreads();
    int c = c0 + threadIdx.x;
    if (c < C) {
        for (int j = threadIdx.y; j < 32; j += 8) {
            g_ft[((size_t)b * NP + n0 + j) * C + c] = tile[threadIdx.x][j];
        }
    }
}

// ---------------- K6: gather into COMPACT (padded) fea, per batch ----------------
__global__ void __launch_bounds__(256) k_gather(int b) {
    int vw = (int)((blockIdx.x * (size_t)blockDim.x + threadIdx.x) >> 5);
    if (vw >= R3) return;
    int idx = (b << 15) + vw;
    int cnt = g_count[idx];
    if (cnt == 0) return;
    int lane = threadIdx.x & 31;
    int gi = g_gidx[idx] + padded_start(b);
    int start = g_offset[idx] - cnt;
    float* out = g_fea + (size_t)gi * C2;
    float mx[8], mn[8];
    #pragma unroll
    for (int i = 0; i < 8; i++) { mx[i] = -CUDART_INF_F; mn[i] = CUDART_INF_F; }
    for (int p = 0; p < cnt; p++) {
        int n = g_plist[(b << 15) + start + p];
        const float* fp = g_ft + ((size_t)(b << 15) + n) * C;
        #pragma unroll
        for (int i = 0; i < 8; i++) {
            int c = i * 32 + lane;
            if (c < C) {
                float x = fp[c];
                mx[i] = fmaxf(mx[i], x);
                mn[i] = fminf(mn[i], x);
            }
        }
    }
    #pragma unroll
    for (int i = 0; i < 8; i++) {
        int c = i * 32 + lane;
        if (c < C) { out[c] = tf32_rna(mx[i]); out[C + c] = tf32_rna(mn[i]); }
    }
}

// ---------------- K7: tf32 mma GEMM (per batch, 128-aligned tiles), BN-stats fused ----------------
#define GSTAGES 3
#define NCHUNK 15
#define STAGE_BYTES 32768
#define SWZ(row, cb) (((row) << 7) + ((cb) ^ (((row) & 7) << 4)))

__global__ void __launch_bounds__(256) k_gemm_mma(const float* __restrict__ bias, int b) {
    int nb = g_boc[b];
    int vloc = blockIdx.y << 7;
    if (vloc >= nb) return;
    int pb = padded_start(b);           // multiple of 128
    int v0 = pb + vloc;                 // 128-aligned tile start
    int vend = pb + nb;
    extern __shared__ char smem[];
    uint32_t sbase = smem_u32(smem);
    int tid = threadIdx.x;
    int warp = tid >> 5, lane = tid & 31;
    int c0 = blockIdx.x << 7;
    const float* fb = g_fea + (size_t)v0 * C2;
    const float* wb = g_wr + (size_t)c0 * C2;

    int warp_m0 = (warp >> 2) << 6;
    int warp_n0 = (warp & 3) << 5;

    float acc[4][4][4];
    #pragma unroll
    for (int i = 0; i < 4; i++)
        #pragma unroll
        for (int j = 0; j < 4; j++)
            #pragma unroll
            for (int k = 0; k < 4; k++) acc[i][j][k] = 0.f;

    int lr = tid >> 1;
    int lj0 = (tid & 1) * 4;

    auto load_chunk = [&](int c, int s) {
        int k0 = c * 32;
        uint32_t sA = sbase + s * STAGE_BYTES;
        uint32_t sB = sA + 16384;
        const float* ga = wb + (size_t)lr * C2 + k0 + lj0 * 4;
        const float* gb = fb + (size_t)lr * C2 + k0 + lj0 * 4;
        #pragma unroll
        for (int jj = 0; jj < 4; jj++) {
            uint32_t off = SWZ((uint32_t)lr, (uint32_t)((lj0 + jj) * 16));
            cp_async16(sA + off, ga + jj * 4);
            cp_async16(sB + off, gb + jj * 4);
        }
    };

    #pragma unroll
    for (int s = 0; s < GSTAGES; s++) {
        load_chunk(s, s);
        asm volatile("cp.async.commit_group;" ::: "memory");
    }
    asm volatile("cp.async.wait_group 2;" ::: "memory");
    __syncthreads();

    for (int c = 0; c < NCHUNK; c++) {
        int s = c % GSTAGES;
        uint32_t sA = sbase + s * STAGE_BYTES;
        uint32_t sB = sA + 16384;
        #pragma unroll
        for (int ks = 0; ks < 4; ks++) {
            uint32_t a[4][4];
            #pragma unroll
            for (int mi = 0; mi < 4; mi++) {
                uint32_t row = (uint32_t)(warp_m0 + mi * 16 + (lane & 15));
                uint32_t cb = (uint32_t)(ks * 32 + ((lane >> 4) << 4));
                ldsm_x4(a[mi], sA + SWZ(row, cb));
            }
            uint32_t bf[2][4];
            #pragma unroll
            for (int p = 0; p < 2; p++) {
                uint32_t row = (uint32_t)(warp_n0 + p * 16 + (lane & 7) + ((lane >> 4) << 3));
                uint32_t cb = (uint32_t)(ks * 32 + (((lane >> 3) & 1) << 4));
                ldsm_x4(bf[p], sB + SWZ(row, cb));
            }
            #pragma unroll
            for (int mi = 0; mi < 4; mi++)
                #pragma unroll
                for (int nf = 0; nf < 4; nf++)
                    mma_tf32(acc[mi][nf], a[mi], bf[nf >> 1][(nf & 1) * 2],
                             bf[nf >> 1][(nf & 1) * 2 + 1]);
        }
        __syncthreads();
        if (c + GSTAGES < NCHUNK) load_chunk(c + GSTAGES, s);
        asm volatile("cp.async.commit_group;" ::: "memory");
        asm volatile("cp.async.wait_group 2;" ::: "memory");
        __syncthreads();
    }

    // epilogue: store compact yc = acc + bias; BN partials masked to v < vend
    #pragma unroll
    for (int mi = 0; mi < 4; mi++) {
        int ch0 = c0 + warp_m0 + mi * 16 + (lane >> 2);
        int ch1 = ch0 + 8;
        float bi0 = (ch0 < C) ? bias[ch0] : 0.f;
        float bi1 = (ch1 < C) ? bias[ch1] : 0.f;
        float* y0 = g_yc + (size_t)(ch0 < C ? ch0 : 0) * NOCCMAX;
        float* y1 = g_yc + (size_t)(ch1 < C ? ch1 : 0) * NOCCMAX;
        float s0 = 0.f, q0 = 0.f, s1 = 0.f, q1 = 0.f;
        #pragma unroll
        for (int nf = 0; nf < 4; nf++) {
            int v = v0 + warp_n0 + nf * 8 + (lane & 3) * 2;
            float a0 = acc[mi][nf][0] + bi0, a1 = acc[mi][nf][1] + bi0;
            float a2 = acc[mi][nf][2] + bi1, a3 = acc[mi][nf][3] + bi1;
            if (ch0 < C) *(float2*)(y0 + v) = make_float2(a0, a1);
            if (ch1 < C) *(float2*)(y1 + v) = make_float2(a2, a3);
            bool m0 = v < vend, m1 = v + 1 < vend;
            s0 += (m0 ? a0 : 0.f) + (m1 ? a1 : 0.f);
            q0 += (m0 ? a0 * a0 : 0.f) + (m1 ? a1 * a1 : 0.f);
            s1 += (m0 ? a2 : 0.f) + (m1 ? a3 : 0.f);
            q1 += (m0 ? a2 * a2 : 0.f) + (m1 ? a3 * a3 : 0.f);
        }
        #pragma unroll
        for (int o = 1; o <= 2; o <<= 1) {
            s0 += __shfl_xor_sync(0xffffffffu, s0, o);
            q0 += __shfl_xor_sync(0xffffffffu, q0, o);
            s1 += __shfl_xor_sync(0xffffffffu, s1, o);
            q1 += __shfl_xor_sync(0xffffffffu, q1, o);
        }
        if ((lane & 3) == 0) {
            if (ch0 < C) { atomicAdd(&g_sum[ch0], s0); atomicAdd(&g_sum2[ch0], q0); }
            if (ch1 < C) { atomicAdd(&g_sum[ch1], s1); atomicAdd(&g_sum2[ch1], q1); }
        }
    }
}

// ---------------- K9: expand compact -> dense + BN-finalize + swish ----------------
__global__ void __launch_bounds__(256) k_out(float* __restrict__ y,
                                             const float* __restrict__ bias,
                                             const float* __restrict__ gamma,
                                             const float* __restrict__ beta) {
    size_t i4 = (size_t)blockIdx.x * blockDim.x + threadIdx.x;
    const size_t TOT4 = (size_t)NB * C * R3 / 4;
    if (i4 >= TOT4) return;
    size_t idx = i4 * 4;
    int bc = (int)(idx >> 15);
    int c = bc % C;
    int b = bc / C;
    int v = (int)(idx & (R3 - 1));
    int nocc = g_boc[0] + g_boc[1] + g_boc[2] + g_boc[3];
    int pb = padded_start(b);

    float bi = bias[c];
    const float invT = 1.0f / (float)(NB * R3);
    float n_e = (float)(NB * R3 - nocc);
    float mean = (g_sum[c] + n_e * bi) * invT;
    float var = (g_sum2[c] + n_e * bi * bi) * invT - mean * mean;
    float A = gamma[c] * rsqrtf(var + BN_EPS);
    float Bv = beta[c] - mean * A;

    int4 g = *(const int4*)(g_gidx + (b << 15) + v);
    const float* yc = g_yc + (size_t)c * NOCCMAX + pb;
    float x0 = (g.x >= 0) ? yc[g.x] : bi;
    float x1 = (g.y >= 0) ? yc[g.y] : bi;
    float x2 = (g.z >= 0) ? yc[g.z] : bi;
    float x3 = (g.w >= 0) ? yc[g.w] : bi;
    x0 = x0 * A + Bv; x1 = x1 * A + Bv; x2 = x2 * A + Bv; x3 = x3 * A + Bv;
    float4 o;
    o.x = x0 / (1.f + __expf(-x0));
    o.y = x1 / (1.f + __expf(-x1));
    o.z = x2 / (1.f + __expf(-x2));
    o.w = x3 / (1.f + __expf(-x3));
    *(float4*)(y + idx) = o;
}

// ---------------- launch ----------------
extern "C" void kernel_launch(void* const* d_in, const int* in_sizes, int n_in,
                              void* d_out, int out_size) {
    const float* features = (const float*)d_in[0];
    const float* coords   = (const float*)d_in[1];
    const float* w        = (const float*)d_in[2];
    const float* bias     = (const float*)d_in[3];
    const float* gamma    = (const float*)d_in[4];
    const float* beta     = (const float*)d_in[5];
    float* out = (float*)d_out;

    const int Y_SIZE = NB * C * R3;
    const int NC_SIZE = NB * 3 * NP;
    int write_nc = (out_size >= Y_SIZE + NC_SIZE) ? 1 : 0;
    float* nc_out = out + Y_SIZE;

    const int GEMM_SMEM = GSTAGES * STAGE_BYTES;   // 96 KB
    static cudaStream_t s1 = nullptr, s2 = nullptr;
    static cudaEvent_t evA = nullptr;
    static cudaEvent_t evT[NB], evG[NB], evM[NB];
    if (!s1) {
        cudaFuncSetAttribute(k_gemm_mma, cudaFuncAttributeMaxDynamicSharedMemorySize,
                             GEMM_SMEM);
        cudaStreamCreateWithFlags(&s1, cudaStreamNonBlocking);
        cudaStreamCreateWithFlags(&s2, cudaStreamNonBlocking);
        cudaEventCreateWithFlags(&evA, cudaEventDisableTiming);
        for (int b = 0; b < NB; b++) {
            cudaEventCreateWithFlags(&evT[b], cudaEventDisableTiming);
            cudaEventCreateWithFlags(&evG[b], cudaEventDisableTiming);
            cudaEventCreateWithFlags(&evM[b], cudaEventDisableTiming);
        }
    }

    // fork: per-batch transposes on s1
    cudaEventRecord(evA, 0);
    cudaStreamWaitEvent(s1, evA, 0);
    for (int b = 0; b < NB; b++) {
        dim3 blk(32, 8);
        dim3 grd(NP / 32, (C + 31) / 32);
        k_transpose<<<grd, blk, 0, s1>>>(features, b);
        cudaEventRecord(evT[b], s1);
    }

    // main chain
    k_setup<<<512, 256>>>(w, coords);
    {
        dim3 grd(NP / 4 / 256, NB);
        k_cmax<<<grd, 256>>>(coords);
    }
    k_voxelize<<<(NB * NP + 255) / 256, 256>>>(coords, nc_out, write_nc);
    k_scan<<<NB, 1024>>>();
    k_scatter<<<(NB * NP + 255) / 256, 256>>>();

    // per-batch gather (main) -> gemm (s2) pipeline
    for (int b = 0; b < NB; b++) {
        cudaStreamWaitEvent(0, evT[b], 0);
        k_gather<<<R3 / 8, 256>>>(b);
        cudaEventRecord(evG[b], 0);
        cudaStreamWaitEvent(s2, evG[b], 0);
        {
            dim3 grd(2, R3 / 128);   // early exit beyond boc[b]
            k_gemm_mma<<<grd, 256, GEMM_SMEM, s2>>>(bias, b);
        }
        cudaEventRecord(evM[b], s2);
    }
    for (int b = 0; b < NB; b++) cudaStreamWaitEvent(0, evM[b], 0);
    {
        size_t tot4 = (size_t)NB * C * R3 / 4;
        k_out<<<(unsigned)((tot4 + 255) / 256), 256>>>(out, bias, gamma, beta);
    }
}

// round 14
// speedup vs baseline: 1.2296x; 1.2296x over previous
#include <cuda_runtime.h>
#include <math_constants.h>
#include <cstdint>

#define RR 32
#define R3 32768
#define C 240
#define C2 480
#define NB 4
#define NP 32768
#define NVOX (NB * R3)
#define NOCCMAX 131072
#define BN_EPS 1e-5f

// ---------------- static scratch ----------------
__device__ float    g_cpart[128][3];
__device__ float    g_meanv[NB][3];
__device__ unsigned g_qmax[NB];
__device__ int   g_pos[NB * NP];
__device__ int   g_count[NVOX];
__device__ int   g_offset[NVOX];
__device__ int   g_gidx[NVOX];          // compact index per voxel (per batch), -1 if empty
__device__ int   g_boc[NB];             // occupied count per batch
__device__ int   g_plist[NB * NP];
__device__ float g_ft[(size_t)NB * NP * C];     // features transposed [B][N][C]
__device__ float g_fea[(size_t)NVOX * C2];      // COMPACT voxel features [gidx][2C]
__device__ float g_yc[(size_t)C * NOCCMAX];     // COMPACT gemm output [c][gidx] (incl bias)
__device__ float g_wr[256 * C2];
__device__ float g_sum[C];
__device__ float g_sum2[C];

// ---------------- helpers ----------------
__device__ __forceinline__ float tf32_rna(float x) {
    uint32_t u; asm("cvt.rna.tf32.f32 %0, %1;" : "=r"(u) : "f"(x));
    return __uint_as_float(u);
}
__device__ __forceinline__ uint32_t smem_u32(const void* p) {
    uint32_t a;
    asm("{ .reg .u64 t; cvta.to.shared.u64 t, %1; cvt.u32.u64 %0, t; }" : "=r"(a) : "l"(p));
    return a;
}
__device__ __forceinline__ void cp_async16(uint32_t dst, const void* src) {
    asm volatile("cp.async.cg.shared.global [%0], [%1], 16;" :: "r"(dst), "l"(src) : "memory");
}
__device__ __forceinline__ void ldsm_x4(uint32_t* r, uint32_t addr) {
    asm volatile("ldmatrix.sync.aligned.m8n8.x4.shared.b16 {%0,%1,%2,%3}, [%4];"
                 : "=r"(r[0]), "=r"(r[1]), "=r"(r[2]), "=r"(r[3]) : "r"(addr));
}
__device__ __forceinline__ void mma_tf32(float* c, const uint32_t* a, uint32_t b0, uint32_t b1) {
    asm volatile("mma.sync.aligned.m16n8k8.row.col.f32.tf32.tf32.f32 "
                 "{%0,%1,%2,%3}, {%4,%5,%6,%7}, {%8,%9}, {%0,%1,%2,%3};"
                 : "+f"(c[0]), "+f"(c[1]), "+f"(c[2]), "+f"(c[3])
                 : "r"(a[0]), "r"(a[1]), "r"(a[2]), "r"(a[3]), "r"(b0), "r"(b1));
}

// ---------------- K_setup ----------------
__global__ void __launch_bounds__(256) k_setup(const float* __restrict__ w,
                                               const float* __restrict__ coords) {
    int i = blockIdx.x * 256 + threadIdx.x;
    if (i < NVOX) g_count[i] = 0;
    if (i < C) { g_sum[i] = 0.f; g_sum2[i] = 0.f; }
    if (i < NB) g_qmax[i] = 0u;
    if (i < 256 * C2) {
        int r = i / C2;
        g_wr[i] = (r < C) ? tf32_rna(w[i]) : 0.f;
    }
    if (blockIdx.x < 128) {
        int b = blockIdx.x >> 5;
        int idx = (blockIdx.x & 31) * 256 + threadIdx.x;
        const float4* cx = (const float4*)(coords + (size_t)b * 3 * NP);
        float4 a = cx[idx];
        float4 c = cx[NP / 4 + idx];
        float4 d = cx[NP / 2 + idx];
        float sx = (a.x + a.y) + (a.z + a.w);
        float sy = (c.x + c.y) + (c.z + c.w);
        float sz = (d.x + d.y) + (d.z + d.w);
        __shared__ float sh[3][8];
        int lane = threadIdx.x & 31, warp = threadIdx.x >> 5;
        #pragma unroll
        for (int o = 16; o; o >>= 1) {
            sx += __shfl_down_sync(0xffffffffu, sx, o);
            sy += __shfl_down_sync(0xffffffffu, sy, o);
            sz += __shfl_down_sync(0xffffffffu, sz, o);
        }
        if (lane == 0) { sh[0][warp] = sx; sh[1][warp] = sy; sh[2][warp] = sz; }
        __syncthreads();
        if (threadIdx.x == 0) {
            float tx = 0.f, ty = 0.f, tz = 0.f;
            #pragma unroll
            for (int j = 0; j < 8; j++) { tx += sh[0][j]; ty += sh[1][j]; tz += sh[2][j]; }
            g_cpart[blockIdx.x][0] = tx;
            g_cpart[blockIdx.x][1] = ty;
            g_cpart[blockIdx.x][2] = tz;
        }
    }
}

// ---------------- K_cmax ----------------
__global__ void __launch_bounds__(256) k_cmax(const float* __restrict__ coords) {
    int b = blockIdx.y;
    __shared__ float mean_s[3];
    if (threadIdx.x < 3) {
        float s = 0.f;
        #pragma unroll
        for (int j = 0; j < 32; j++) s += g_cpart[(b << 5) + j][threadIdx.x];
        float m = s * (1.0f / (float)NP);
        mean_s[threadIdx.x] = m;
        if (blockIdx.x == 0) g_meanv[b][threadIdx.x] = m;
    }
    __syncthreads();
    float m0 = mean_s[0], m1 = mean_s[1], m2 = mean_s[2];
    int idx = blockIdx.x * blockDim.x + threadIdx.x;
    const float4* cx = (const float4*)(coords + (size_t)b * 3 * NP);
    float4 a = cx[idx];
    float4 c = cx[NP / 4 + idx];
    float4 d = cx[NP / 2 + idx];
    float mx = 0.f, dx, dy, dz, q;
    dx = a.x - m0; dy = c.x - m1; dz = d.x - m2; q = dx*dx + dy*dy + dz*dz; mx = fmaxf(mx, q);
    dx = a.y - m0; dy = c.y - m1; dz = d.y - m2; q = dx*dx + dy*dy + dz*dz; mx = fmaxf(mx, q);
    dx = a.z - m0; dy = c.z - m1; dz = d.z - m2; q = dx*dx + dy*dy + dz*dz; mx = fmaxf(mx, q);
    dx = a.w - m0; dy = c.w - m1; dz = d.w - m2; q = dx*dx + dy*dy + dz*dz; mx = fmaxf(mx, q);
    __shared__ float sh[8];
    int lane = threadIdx.x & 31, warp = threadIdx.x >> 5;
    #pragma unroll
    for (int o = 16; o; o >>= 1) mx = fmaxf(mx, __shfl_down_sync(0xffffffffu, mx, o));
    if (lane == 0) sh[warp] = mx;
    __syncthreads();
    if (threadIdx.x == 0) {
        float t = 0.f;
        #pragma unroll
        for (int j = 0; j < 8; j++) t = fmaxf(t, sh[j]);
        atomicMax(&g_qmax[b], __float_as_uint(t));
    }
}

// ---------------- K2: nc + voxel id + count ----------------
__global__ void __launch_bounds__(256) k_voxelize(const float* __restrict__ coords,
                                                  float* __restrict__ nc_out, int write_nc) {
    int i = blockIdx.x * blockDim.x + threadIdx.x;
    if (i >= NB * NP) return;
    int b = i >> 15, n = i & (NP - 1);
    const float* base = coords + (size_t)b * 3 * NP;
    float sc = sqrtf(__uint_as_float(g_qmax[b])) * 2.0f;
    int vx[3];
    #pragma unroll
    for (int ch = 0; ch < 3; ch++) {
        float x = base[ch * NP + n];
        float u = (x - g_meanv[b][ch]) / sc + 0.5f;
        float t = fminf(fmaxf(u * (float)RR, 0.0f), (float)(RR - 1));
        if (write_nc) nc_out[((size_t)b * 3 + ch) * NP + n] = t;
        vx[ch] = (int)rintf(t);
    }
    int pos = vx[0] + vx[1] * RR + vx[2] * RR * RR;
    g_pos[i] = pos;
    atomicAdd(&g_count[(b << 15) + pos], 1);
}

// ---------------- K3: per-batch dual scan (points + occupancy) ----------------
__global__ void __launch_bounds__(1024) k_scan() {
    int b = blockIdx.x;
    int t = threadIdx.x;
    int base = b * R3 + t * 32;
    int4 v[8];
    const int4* src = (const int4*)(g_count + base);
    #pragma unroll
    for (int j = 0; j < 8; j++) v[j] = src[j];
    unsigned comb = 0;
    #pragma unroll
    for (int j = 0; j < 8; j++) {
        comb += ((unsigned)(v[j].x) << 16) + (v[j].x > 0);
        comb += ((unsigned)(v[j].y) << 16) + (v[j].y > 0);
        comb += ((unsigned)(v[j].z) << 16) + (v[j].z > 0);
        comb += ((unsigned)(v[j].w) << 16) + (v[j].w > 0);
    }
    __shared__ unsigned warp_sums[32];
    int lane = t & 31, warp = t >> 5;
    unsigned inc = comb;
    #pragma unroll
    for (int o = 1; o < 32; o <<= 1) {
        unsigned u = __shfl_up_sync(0xffffffffu, inc, o);
        if (lane >= o) inc += u;
    }
    if (lane == 31) warp_sums[warp] = inc;
    __syncthreads();
    if (warp == 0) {
        unsigned w = warp_sums[lane];
        #pragma unroll
        for (int o = 1; o < 32; o <<= 1) {
            unsigned u = __shfl_up_sync(0xffffffffu, w, o);
            if (lane >= o) w += u;
        }
        warp_sums[lane] = w;
    }
    __syncthreads();
    unsigned excl = inc - comb + (warp ? warp_sums[warp - 1] : 0u);
    int run_pts = (int)(excl >> 16);
    int run_occ = (int)(excl & 0xFFFFu);
    int4* dsto = (int4*)(g_offset + base);
    int4* dstg = (int4*)(g_gidx + base);
    #pragma unroll
    for (int j = 0; j < 8; j++) {
        int4 o, g;
        o.x = run_pts; g.x = (v[j].x > 0) ? run_occ : -1; run_pts += v[j].x; run_occ += (v[j].x > 0);
        o.y = run_pts; g.y = (v[j].y > 0) ? run_occ : -1; run_pts += v[j].y; run_occ += (v[j].y > 0);
        o.z = run_pts; g.z = (v[j].z > 0) ? run_occ : -1; run_pts += v[j].z; run_occ += (v[j].z > 0);
        o.w = run_pts; g.w = (v[j].w > 0) ? run_occ : -1; run_pts += v[j].w; run_occ += (v[j].w > 0);
        dsto[j] = o;
        dstg[j] = g;
    }
    if (t == 1023) g_boc[b] = run_occ;
}

// ---------------- K4: scatter ----------------
__global__ void __launch_bounds__(256) k_scatter() {
    int i = blockIdx.x * blockDim.x + threadIdx.x;
    if (i >= NB * NP) return;
    int b = i >> 15, n = i & (NP - 1);
    int pos = g_pos[i];
    int slot = atomicAdd(&g_offset[(b << 15) + pos], 1);
    g_plist[(b << 15) + slot] = n;
}

// ---------------- K5: transpose [B,C,N] -> [B,N,C], float4 both directions ----------------
// tile = 32 c x 128 n; smem [c][n] row stride 132 floats (16B aligned rows).
__global__ void __launch_bounds__(256) k_transpose(const float* __restrict__ f) {
    __shared__ float tile[32][132];
    int b = blockIdx.z;
    int c0 = blockIdx.y * 32, n0 = blockIdx.x * 128;
    int t = threadIdx.x;
    // load: 8 c-rows x 32 float4 per iteration, 4 iterations
    int cl = t >> 5;            // 0..7
    int nl = (t & 31) * 4;      // 0..124
    #pragma unroll
    for (int j = 0; j < 4; j++) {
        int c = c0 + j * 8 + cl;
        float4 v = make_float4(0.f, 0.f, 0.f, 0.f);
        if (c < C) v = *(const float4*)(f + ((size_t)b * C + c) * NP + n0 + nl);
        *(float4*)&tile[j * 8 + cl][nl] = v;
    }
    __syncthreads();
    // write: 32 n-rows x 8 c-float4 per iteration, 4 iterations
    int nw = t >> 3;            // 0..31
    int cw = (t & 7) * 4;       // 0..28
    #pragma unroll
    for (int j = 0; j < 4; j++) {
        int n = n0 + j * 32 + nw;
        int c = c0 + cw;
        if (c < C) {            // C%4==0 and c%4==0 => c+3 < C
            int nf = j * 32 + nw;
            float4 o;
            o.x = tile[cw + 0][nf];
            o.y = tile[cw + 1][nf];
            o.z = tile[cw + 2][nf];
            o.w = tile[cw + 3][nf];
            *(float4*)(g_ft + ((size_t)b * NP + n) * C + c) = o;
        }
    }
}

// ---------------- K6: gather into COMPACT fea (occupied voxels only) ----------------
__global__ void __launch_bounds__(256) k_gather() {
    int gw = (int)((blockIdx.x * (size_t)blockDim.x + threadIdx.x) >> 5);
    if (gw >= NVOX) return;
    int idx = gw;
    int cnt = g_count[idx];
    if (cnt == 0) return;
    int lane = threadIdx.x & 31;
    int b = gw >> 15;
    int pb = 0;
    #pragma unroll
    for (int j = 0; j < NB; j++) pb += (j < b) ? g_boc[j] : 0;
    int gi = g_gidx[idx] + pb;
    int start = g_offset[idx] - cnt;
    float* out = g_fea + (size_t)gi * C2;
    float mx[8], mn[8];
    #pragma unroll
    for (int i = 0; i < 8; i++) { mx[i] = -CUDART_INF_F; mn[i] = CUDART_INF_F; }
    for (int p = 0; p < cnt; p++) {
        int n = g_plist[(b << 15) + start + p];
        const float* fp = g_ft + ((size_t)(b << 15) + n) * C;
        #pragma unroll
        for (int i = 0; i < 8; i++) {
            int c = i * 32 + lane;
            if (c < C) {
                float x = fp[c];
                mx[i] = fmaxf(mx[i], x);
                mn[i] = fminf(mn[i], x);
            }
        }
    }
    #pragma unroll
    for (int i = 0; i < 8; i++) {
        int c = i * 32 + lane;
        if (c < C) { out[c] = tf32_rna(mx[i]); out[C + c] = tf32_rna(mn[i]); }
    }
}

// ---------------- K7: tf32 mma GEMM over compact columns, BN-stats fused ----------------
#define GSTAGES 3
#define NCHUNK 15
#define STAGE_BYTES 32768
#define SWZ(row, cb) (((row) << 7) + ((cb) ^ (((row) & 7) << 4)))

__global__ void __launch_bounds__(256) k_gemm_mma(const float* __restrict__ bias) {
    int nocc = g_boc[0] + g_boc[1] + g_boc[2] + g_boc[3];
    int v0 = blockIdx.y << 7;
    if (v0 >= nocc) return;
    extern __shared__ char smem[];
    uint32_t sbase = smem_u32(smem);
    int tid = threadIdx.x;
    int warp = tid >> 5, lane = tid & 31;
    int c0 = blockIdx.x << 7;
    const float* fb = g_fea + (size_t)v0 * C2;
    const float* wb = g_wr + (size_t)c0 * C2;

    int warp_m0 = (warp >> 2) << 6;
    int warp_n0 = (warp & 3) << 5;

    float acc[4][4][4];
    #pragma unroll
    for (int i = 0; i < 4; i++)
        #pragma unroll
        for (int j = 0; j < 4; j++)
            #pragma unroll
            for (int k = 0; k < 4; k++) acc[i][j][k] = 0.f;

    int lr = tid >> 1;
    int lj0 = (tid & 1) * 4;

    auto load_chunk = [&](int c, int s) {
        int k0 = c * 32;
        uint32_t sA = sbase + s * STAGE_BYTES;
        uint32_t sB = sA + 16384;
        const float* ga = wb + (size_t)lr * C2 + k0 + lj0 * 4;
        const float* gb = fb + (size_t)lr * C2 + k0 + lj0 * 4;
        #pragma unroll
        for (int jj = 0; jj < 4; jj++) {
            uint32_t off = SWZ((uint32_t)lr, (uint32_t)((lj0 + jj) * 16));
            cp_async16(sA + off, ga + jj * 4);
            cp_async16(sB + off, gb + jj * 4);
        }
    };

    #pragma unroll
    for (int s = 0; s < GSTAGES; s++) {
        load_chunk(s, s);
        asm volatile("cp.async.commit_group;" ::: "memory");
    }
    asm volatile("cp.async.wait_group 2;" ::: "memory");
    __syncthreads();

    for (int c = 0; c < NCHUNK; c++) {
        int s = c % GSTAGES;
        uint32_t sA = sbase + s * STAGE_BYTES;
        uint32_t sB = sA + 16384;
        #pragma unroll
        for (int ks = 0; ks < 4; ks++) {
            uint32_t a[4][4];
            #pragma unroll
            for (int mi = 0; mi < 4; mi++) {
                uint32_t row = (uint32_t)(warp_m0 + mi * 16 + (lane & 15));
                uint32_t cb = (uint32_t)(ks * 32 + ((lane >> 4) << 4));
                ldsm_x4(a[mi], sA + SWZ(row, cb));
            }
            uint32_t bf[2][4];
            #pragma unroll
            for (int p = 0; p < 2; p++) {
                uint32_t row = (uint32_t)(warp_n0 + p * 16 + (lane & 7) + ((lane >> 4) << 3));
                uint32_t cb = (uint32_t)(ks * 32 + (((lane >> 3) & 1) << 4));
                ldsm_x4(bf[p], sB + SWZ(row, cb));
            }
            #pragma unroll
            for (int mi = 0; mi < 4; mi++)
                #pragma unroll
                for (int nf = 0; nf < 4; nf++)
                    mma_tf32(acc[mi][nf], a[mi], bf[nf >> 1][(nf & 1) * 2],
                             bf[nf >> 1][(nf & 1) * 2 + 1]);
        }
        __syncthreads();
        if (c + GSTAGES < NCHUNK) load_chunk(c + GSTAGES, s);
        asm volatile("cp.async.commit_group;" ::: "memory");
        asm volatile("cp.async.wait_group 2;" ::: "memory");
        __syncthreads();
    }

    // epilogue: store compact yc = acc + bias; BN partials masked to v < nocc
    #pragma unroll
    for (int mi = 0; mi < 4; mi++) {
        int ch0 = c0 + warp_m0 + mi * 16 + (lane >> 2);
        int ch1 = ch0 + 8;
        float bi0 = (ch0 < C) ? bias[ch0] : 0.f;
        float bi1 = (ch1 < C) ? bias[ch1] : 0.f;
        float* y0 = g_yc + (size_t)(ch0 < C ? ch0 : 0) * NOCCMAX;
        float* y1 = g_yc + (size_t)(ch1 < C ? ch1 : 0) * NOCCMAX;
        float s0 = 0.f, q0 = 0.f, s1 = 0.f, q1 = 0.f;
        #pragma unroll
        for (int nf = 0; nf < 4; nf++) {
            int v = v0 + warp_n0 + nf * 8 + (lane & 3) * 2;
            float a0 = acc[mi][nf][0] + bi0, a1 = acc[mi][nf][1] + bi0;
            float a2 = acc[mi][nf][2] + bi1, a3 = acc[mi][nf][3] + bi1;
            if (ch0 < C) *(float2*)(y0 + v) = make_float2(a0, a1);
            if (ch1 < C) *(float2*)(y1 + v) = make_float2(a2, a3);
            bool m0 = v < nocc, m1 = v + 1 < nocc;
            s0 += (m0 ? a0 : 0.f) + (m1 ? a1 : 0.f);
            q0 += (m0 ? a0 * a0 : 0.f) + (m1 ? a1 * a1 : 0.f);
            s1 += (m0 ? a2 : 0.f) + (m1 ? a3 : 0.f);
            q1 += (m0 ? a2 * a2 : 0.f) + (m1 ? a3 * a3 : 0.f);
        }
        #pragma unroll
        for (int o = 1; o <= 2; o <<= 1) {
            s0 += __shfl_xor_sync(0xffffffffu, s0, o);
            q0 += __shfl_xor_sync(0xffffffffu, q0, o);
            s1 += __shfl_xor_sync(0xffffffffu, s1, o);
            q1 += __shfl_xor_sync(0xffffffffu, q1, o);
        }
        if ((lane & 3) == 0) {
            if (ch0 < C) { atomicAdd(&g_sum[ch0], s0); atomicAdd(&g_sum2[ch0], q0); }
            if (ch1 < C) { atomicAdd(&g_sum[ch1], s1); atomicAdd(&g_sum2[ch1], q1); }
        }
    }
}

// ---------------- K9: expand compact -> dense + BN-finalize + swish ----------------
__global__ void __launch_bounds__(256) k_out(float* __restrict__ y,
                                             const float* __restrict__ bias,
                                             const float* __restrict__ gamma,
                                             const float* __restrict__ beta) {
    size_t i4 = (size_t)blockIdx.x * blockDim.x + threadIdx.x;
    const size_t TOT4 = (size_t)NB * C * R3 / 4;
    if (i4 >= TOT4) return;
    size_t idx = i4 * 4;
    int bc = (int)(idx >> 15);
    int c = bc % C;
    int b = bc / C;
    int v = (int)(idx & (R3 - 1));
    int nocc = g_boc[0] + g_boc[1] + g_boc[2] + g_boc[3];
    int pb = 0;
    #pragma unroll
    for (int j = 0; j < NB; j++) pb += (j < b) ? g_boc[j] : 0;

    float bi = bias[c];
    const float invT = 1.0f / (float)(NB * R3);
    float n_e = (float)(NB * R3 - nocc);
    float mean = (g_sum[c] + n_e * bi) * invT;
    float var = (g_sum2[c] + n_e * bi * bi) * invT - mean * mean;
    float A = gamma[c] * rsqrtf(var + BN_EPS);
    float Bv = beta[c] - mean * A;

    int4 g = *(const int4*)(g_gidx + (b << 15) + v);
    const float* yc = g_yc + (size_t)c * NOCCMAX + pb;
    float x0 = (g.x >= 0) ? yc[g.x] : bi;
    float x1 = (g.y >= 0) ? yc[g.y] : bi;
    float x2 = (g.z >= 0) ? yc[g.z] : bi;
    float x3 = (g.w >= 0) ? yc[g.w] : bi;
    x0 = x0 * A + Bv; x1 = x1 * A + Bv; x2 = x2 * A + Bv; x3 = x3 * A + Bv;
    float4 o;
    o.x = x0 / (1.f + __expf(-x0));
    o.y = x1 / (1.f + __expf(-x1));
    o.z = x2 / (1.f + __expf(-x2));
    o.w = x3 / (1.f + __expf(-x3));
    *(float4*)(y + idx) = o;
}

// ---------------- launch ----------------
extern "C" void kernel_launch(void* const* d_in, const int* in_sizes, int n_in,
                              void* d_out, int out_size) {
    const float* features = (const float*)d_in[0];
    const float* coords   = (const float*)d_in[1];
    const float* w        = (const float*)d_in[2];
    const float* bias     = (const float*)d_in[3];
    const float* gamma    = (const float*)d_in[4];
    const float* beta     = (const float*)d_in[5];
    float* out = (float*)d_out;

    const int Y_SIZE = NB * C * R3;
    const int NC_SIZE = NB * 3 * NP;
    int write_nc = (out_size >= Y_SIZE + NC_SIZE) ? 1 : 0;
    float* nc_out = out + Y_SIZE;

    const int GEMM_SMEM = GSTAGES * STAGE_BYTES;   // 96 KB
    static cudaStream_t s1 = nullptr;
    static cudaEvent_t evA = nullptr, evT = nullptr;
    if (!s1) {
        cudaFuncSetAttribute(k_gemm_mma, cudaFuncAttributeMaxDynamicSharedMemorySize,
                             GEMM_SMEM);
        cudaStreamCreateWithFlags(&s1, cudaStreamNonBlocking);
        cudaEventCreateWithFlags(&evA, cudaEventDisableTiming);
        cudaEventCreateWithFlags(&evT, cudaEventDisableTiming);
    }

    // fork: monolithic transpose on s1 overlaps the voxel chain
    cudaEventRecord(evA, 0);
    cudaStreamWaitEvent(s1, evA, 0);
    {
        dim3 grd(NP / 128, 8, NB);
        k_transpose<<<grd, 256, 0, s1>>>(features);
    }
    cudaEventRecord(evT, s1);

    // main chain
    k_setup<<<512, 256>>>(w, coords);
    {
        dim3 grd(NP / 4 / 256, NB);
        k_cmax<<<grd, 256>>>(coords);
    }
    k_voxelize<<<(NB * NP + 255) / 256, 256>>>(coords, nc_out, write_nc);
    k_scan<<<NB, 1024>>>();
    k_scatter<<<(NB * NP + 255) / 256, 256>>>();

    // join: gather needs both scatter (main) and transpose (s1)
    cudaStreamWaitEvent(0, evT, 0);
    k_gather<<<(NVOX) / 8, 256>>>();
    {
        dim3 grd(2, NOCCMAX / 128);   // CTAs beyond nocc early-exit
        k_gemm_mma<<<grd, 256, GEMM_SMEM>>>(bias);
    }
    {
        size_t tot4 = (size_t)NB * C * R3 / 4;
        k_out<<<(unsigned)((tot4 + 255) / 256), 256>>>(out, bias, gamma, beta);
    }
}

// round 15
// speedup vs baseline: 1.2693x; 1.0323x over previous
#include <cuda_runtime.h>
#include <math_constants.h>
#include <cstdint>

#define RR 32
#define R3 32768
#define C 240
#define C2 480
#define NB 4
#define NP 32768
#define NVOX (NB * R3)
#define NOCCMAX 131072
#define BN_EPS 1e-5f

// ---------------- static scratch ----------------
__device__ float    g_cpart[128][3];
__device__ float    g_meanv[NB][3];
__device__ unsigned g_qmax[NB];
__device__ int   g_pos[NB * NP];
__device__ int   g_count[NVOX];
__device__ int   g_offset[NVOX];
__device__ int   g_gidx[NVOX];          // compact index per voxel (per batch), -1 if empty
__device__ int   g_boc[NB];             // occupied count per batch
__device__ int   g_plist[NB * NP];
__device__ float g_ft[(size_t)NB * NP * C];     // features transposed [B][N][C]
__device__ float g_fea[(size_t)NVOX * C2];      // COMPACT voxel features [gidx][2C]
__device__ float g_yc[(size_t)C * NOCCMAX];     // COMPACT gemm output [c][gidx] (incl bias)
__device__ float g_wr[256 * C2];
__device__ float g_sum[C];
__device__ float g_sum2[C];
__device__ float g_bnA[C];
__device__ float g_bnB[C];

// ---------------- helpers ----------------
__device__ __forceinline__ float tf32_rna(float x) {
    uint32_t u; asm("cvt.rna.tf32.f32 %0, %1;" : "=r"(u) : "f"(x));
    return __uint_as_float(u);
}
__device__ __forceinline__ uint32_t smem_u32(const void* p) {
    uint32_t a;
    asm("{ .reg .u64 t; cvta.to.shared.u64 t, %1; cvt.u32.u64 %0, t; }" : "=r"(a) : "l"(p));
    return a;
}
__device__ __forceinline__ void cp_async16(uint32_t dst, const void* src) {
    asm volatile("cp.async.cg.shared.global [%0], [%1], 16;" :: "r"(dst), "l"(src) : "memory");
}
__device__ __forceinline__ void ldsm_x4(uint32_t* r, uint32_t addr) {
    asm volatile("ldmatrix.sync.aligned.m8n8.x4.shared.b16 {%0,%1,%2,%3}, [%4];"
                 : "=r"(r[0]), "=r"(r[1]), "=r"(r[2]), "=r"(r[3]) : "r"(addr));
}
__device__ __forceinline__ void mma_tf32(float* c, const uint32_t* a, uint32_t b0, uint32_t b1) {
    asm volatile("mma.sync.aligned.m16n8k8.row.col.f32.tf32.tf32.f32 "
                 "{%0,%1,%2,%3}, {%4,%5,%6,%7}, {%8,%9}, {%0,%1,%2,%3};"
                 : "+f"(c[0]), "+f"(c[1]), "+f"(c[2]), "+f"(c[3])
                 : "r"(a[0]), "r"(a[1]), "r"(a[2]), "r"(a[3]), "r"(b0), "r"(b1));
}

// ---------------- K_setup ----------------
__global__ void __launch_bounds__(256) k_setup(const float* __restrict__ w,
                                               const float* __restrict__ coords) {
    int i = blockIdx.x * 256 + threadIdx.x;
    if (i < NVOX) g_count[i] = 0;
    if (i < C) { g_sum[i] = 0.f; g_sum2[i] = 0.f; }
    if (i < NB) g_qmax[i] = 0u;
    if (i < 256 * C2) {
        int r = i / C2;
        g_wr[i] = (r < C) ? tf32_rna(w[i]) : 0.f;
    }
    if (blockIdx.x < 128) {
        int b = blockIdx.x >> 5;
        int idx = (blockIdx.x & 31) * 256 + threadIdx.x;
        const float4* cx = (const float4*)(coords + (size_t)b * 3 * NP);
        float4 a = cx[idx];
        float4 c = cx[NP / 4 + idx];
        float4 d = cx[NP / 2 + idx];
        float sx = (a.x + a.y) + (a.z + a.w);
        float sy = (c.x + c.y) + (c.z + c.w);
        float sz = (d.x + d.y) + (d.z + d.w);
        __shared__ float sh[3][8];
        int lane = threadIdx.x & 31, warp = threadIdx.x >> 5;
        #pragma unroll
        for (int o = 16; o; o >>= 1) {
            sx += __shfl_down_sync(0xffffffffu, sx, o);
            sy += __shfl_down_sync(0xffffffffu, sy, o);
            sz += __shfl_down_sync(0xffffffffu, sz, o);
        }
        if (lane == 0) { sh[0][warp] = sx; sh[1][warp] = sy; sh[2][warp] = sz; }
        __syncthreads();
        if (threadIdx.x == 0) {
            float tx = 0.f, ty = 0.f, tz = 0.f;
            #pragma unroll
            for (int j = 0; j < 8; j++) { tx += sh[0][j]; ty += sh[1][j]; tz += sh[2][j]; }
            g_cpart[blockIdx.x][0] = tx;
            g_cpart[blockIdx.x][1] = ty;
            g_cpart[blockIdx.x][2] = tz;
        }
    }
}

// ---------------- K_cmax ----------------
__global__ void __launch_bounds__(256) k_cmax(const float* __restrict__ coords) {
    int b = blockIdx.y;
    __shared__ float mean_s[3];
    if (threadIdx.x < 3) {
        float s = 0.f;
        #pragma unroll
        for (int j = 0; j < 32; j++) s += g_cpart[(b << 5) + j][threadIdx.x];
        float m = s * (1.0f / (float)NP);
        mean_s[threadIdx.x] = m;
        if (blockIdx.x == 0) g_meanv[b][threadIdx.x] = m;
    }
    __syncthreads();
    float m0 = mean_s[0], m1 = mean_s[1], m2 = mean_s[2];
    int idx = blockIdx.x * blockDim.x + threadIdx.x;
    const float4* cx = (const float4*)(coords + (size_t)b * 3 * NP);
    float4 a = cx[idx];
    float4 c = cx[NP / 4 + idx];
    float4 d = cx[NP / 2 + idx];
    float mx = 0.f, dx, dy, dz, q;
    dx = a.x - m0; dy = c.x - m1; dz = d.x - m2; q = dx*dx + dy*dy + dz*dz; mx = fmaxf(mx, q);
    dx = a.y - m0; dy = c.y - m1; dz = d.y - m2; q = dx*dx + dy*dy + dz*dz; mx = fmaxf(mx, q);
    dx = a.z - m0; dy = c.z - m1; dz = d.z - m2; q = dx*dx + dy*dy + dz*dz; mx = fmaxf(mx, q);
    dx = a.w - m0; dy = c.w - m1; dz = d.w - m2; q = dx*dx + dy*dy + dz*dz; mx = fmaxf(mx, q);
    __shared__ float sh[8];
    int lane = threadIdx.x & 31, warp = threadIdx.x >> 5;
    #pragma unroll
    for (int o = 16; o; o >>= 1) mx = fmaxf(mx, __shfl_down_sync(0xffffffffu, mx, o));
    if (lane == 0) sh[warp] = mx;
    __syncthreads();
    if (threadIdx.x == 0) {
        float t = 0.f;
        #pragma unroll
        for (int j = 0; j < 8; j++) t = fmaxf(t, sh[j]);
        atomicMax(&g_qmax[b], __float_as_uint(t));
    }
}

// ---------------- K2: nc + voxel id + count ----------------
__global__ void __launch_bounds__(256) k_voxelize(const float* __restrict__ coords,
                                                  float* __restrict__ nc_out, int write_nc) {
    int i = blockIdx.x * blockDim.x + threadIdx.x;
    if (i >= NB * NP) return;
    int b = i >> 15, n = i & (NP - 1);
    const float* base = coords + (size_t)b * 3 * NP;
    float sc = sqrtf(__uint_as_float(g_qmax[b])) * 2.0f;
    int vx[3];
    #pragma unroll
    for (int ch = 0; ch < 3; ch++) {
        float x = base[ch * NP + n];
        float u = (x - g_meanv[b][ch]) / sc + 0.5f;
        float t = fminf(fmaxf(u * (float)RR, 0.0f), (float)(RR - 1));
        if (write_nc) nc_out[((size_t)b * 3 + ch) * NP + n] = t;
        vx[ch] = (int)rintf(t);
    }
    int pos = vx[0] + vx[1] * RR + vx[2] * RR * RR;
    g_pos[i] = pos;
    atomicAdd(&g_count[(b << 15) + pos], 1);
}

// ---------------- K3: per-batch dual scan (points + occupancy) ----------------
__global__ void __launch_bounds__(1024) k_scan() {
    int b = blockIdx.x;
    int t = threadIdx.x;
    int base = b * R3 + t * 32;
    int4 v[8];
    const int4* src = (const int4*)(g_count + base);
    #pragma unroll
    for (int j = 0; j < 8; j++) v[j] = src[j];
    unsigned comb = 0;
    #pragma unroll
    for (int j = 0; j < 8; j++) {
        comb += ((unsigned)(v[j].x) << 16) + (v[j].x > 0);
        comb += ((unsigned)(v[j].y) << 16) + (v[j].y > 0);
        comb += ((unsigned)(v[j].z) << 16) + (v[j].z > 0);
        comb += ((unsigned)(v[j].w) << 16) + (v[j].w > 0);
    }
    __shared__ unsigned warp_sums[32];
    int lane = t & 31, warp = t >> 5;
    unsigned inc = comb;
    #pragma unroll
    for (int o = 1; o < 32; o <<= 1) {
        unsigned u = __shfl_up_sync(0xffffffffu, inc, o);
        if (lane >= o) inc += u;
    }
    if (lane == 31) warp_sums[warp] = inc;
    __syncthreads();
    if (warp == 0) {
        unsigned w = warp_sums[lane];
        #pragma unroll
        for (int o = 1; o < 32; o <<= 1) {
            unsigned u = __shfl_up_sync(0xffffffffu, w, o);
            if (lane >= o) w += u;
        }
        warp_sums[lane] = w;
    }
    __syncthreads();
    unsigned excl = inc - comb + (warp ? warp_sums[warp - 1] : 0u);
    int run_pts = (int)(excl >> 16);
    int run_occ = (int)(excl & 0xFFFFu);
    int4* dsto = (int4*)(g_offset + base);
    int4* dstg = (int4*)(g_gidx + base);
    #pragma unroll
    for (int j = 0; j < 8; j++) {
        int4 o, g;
        o.x = run_pts; g.x = (v[j].x > 0) ? run_occ : -1; run_pts += v[j].x; run_occ += (v[j].x > 0);
        o.y = run_pts; g.y = (v[j].y > 0) ? run_occ : -1; run_pts += v[j].y; run_occ += (v[j].y > 0);
        o.z = run_pts; g.z = (v[j].z > 0) ? run_occ : -1; run_pts += v[j].z; run_occ += (v[j].z > 0);
        o.w = run_pts; g.w = (v[j].w > 0) ? run_occ : -1; run_pts += v[j].w; run_occ += (v[j].w > 0);
        dsto[j] = o;
        dstg[j] = g;
    }
    if (t == 1023) g_boc[b] = run_occ;
}

// ---------------- K4: scatter ----------------
__global__ void __launch_bounds__(256) k_scatter() {
    int i = blockIdx.x * blockDim.x + threadIdx.x;
    if (i >= NB * NP) return;
    int b = i >> 15, n = i & (NP - 1);
    int pos = g_pos[i];
    int slot = atomicAdd(&g_offset[(b << 15) + pos], 1);
    g_plist[(b << 15) + slot] = n;
}

// ---------------- K5: transpose [B,C,N] -> [B,N,C], float4 both directions ----------------
__global__ void __launch_bounds__(256) k_transpose(const float* __restrict__ f) {
    __shared__ float tile[32][132];
    int b = blockIdx.z;
    int c0 = blockIdx.y * 32, n0 = blockIdx.x * 128;
    int t = threadIdx.x;
    int cl = t >> 5;
    int nl = (t & 31) * 4;
    #pragma unroll
    for (int j = 0; j < 4; j++) {
        int c = c0 + j * 8 + cl;
        float4 v = make_float4(0.f, 0.f, 0.f, 0.f);
        if (c < C) v = *(const float4*)(f + ((size_t)b * C + c) * NP + n0 + nl);
        *(float4*)&tile[j * 8 + cl][nl] = v;
    }
    __syncthreads();
    int nw = t >> 3;
    int cw = (t & 7) * 4;
    #pragma unroll
    for (int j = 0; j < 4; j++) {
        int n = n0 + j * 32 + nw;
        int c = c0 + cw;
        if (c < C) {
            int nf = j * 32 + nw;
            float4 o;
            o.x = tile[cw + 0][nf];
            o.y = tile[cw + 1][nf];
            o.z = tile[cw + 2][nf];
            o.w = tile[cw + 3][nf];
            *(float4*)(g_ft + ((size_t)b * NP + n) * C + c) = o;
        }
    }
}

// ---------------- K6: gather into COMPACT fea, float4 channels ----------------
// C = 240 floats = 60 float4; lane i handles float4 index c4 = i*32+lane (< 60).
__global__ void __launch_bounds__(256) k_gather() {
    int gw = (int)((blockIdx.x * (size_t)blockDim.x + threadIdx.x) >> 5);
    if (gw >= NVOX) return;
    int idx = gw;
    int cnt = g_count[idx];
    if (cnt == 0) return;
    int lane = threadIdx.x & 31;
    int b = gw >> 15;
    int pb = 0;
    #pragma unroll
    for (int j = 0; j < NB; j++) pb += (j < b) ? g_boc[j] : 0;
    int gi = g_gidx[idx] + pb;
    int start = g_offset[idx] - cnt;
    float4* out4 = (float4*)(g_fea + (size_t)gi * C2);     // 120 float4: [0,60) max, [60,120) min
    float4 mx4[2], mn4[2];
    #pragma unroll
    for (int i = 0; i < 2; i++) {
        mx4[i] = make_float4(-CUDART_INF_F, -CUDART_INF_F, -CUDART_INF_F, -CUDART_INF_F);
        mn4[i] = make_float4(CUDART_INF_F, CUDART_INF_F, CUDART_INF_F, CUDART_INF_F);
    }
    for (int p = 0; p < cnt; p++) {
        int n = g_plist[(b << 15) + start + p];
        const float4* fp4 = (const float4*)(g_ft + ((size_t)(b << 15) + n) * C);
        #pragma unroll
        for (int i = 0; i < 2; i++) {
            int c4 = i * 32 + lane;
            if (c4 < 60) {
                float4 x = fp4[c4];
                mx4[i].x = fmaxf(mx4[i].x, x.x); mn4[i].x = fminf(mn4[i].x, x.x);
                mx4[i].y = fmaxf(mx4[i].y, x.y); mn4[i].y = fminf(mn4[i].y, x.y);
                mx4[i].z = fmaxf(mx4[i].z, x.z); mn4[i].z = fminf(mn4[i].z, x.z);
                mx4[i].w = fmaxf(mx4[i].w, x.w); mn4[i].w = fminf(mn4[i].w, x.w);
            }
        }
    }
    #pragma unroll
    for (int i = 0; i < 2; i++) {
        int c4 = i * 32 + lane;
        if (c4 < 60) {
            float4 a, d;
            a.x = tf32_rna(mx4[i].x); a.y = tf32_rna(mx4[i].y);
            a.z = tf32_rna(mx4[i].z); a.w = tf32_rna(mx4[i].w);
            d.x = tf32_rna(mn4[i].x); d.y = tf32_rna(mn4[i].y);
            d.z = tf32_rna(mn4[i].z); d.w = tf32_rna(mn4[i].w);
            out4[c4] = a;
            out4[60 + c4] = d;
        }
    }
}

// ---------------- K7: tf32 mma GEMM over compact columns, BN-stats fused ----------------
#define GSTAGES 3
#define NCHUNK 15
#define STAGE_BYTES 32768
#define SWZ(row, cb) (((row) << 7) + ((cb) ^ (((row) & 7) << 4)))

__global__ void __launch_bounds__(256) k_gemm_mma(const float* __restrict__ bias) {
    int nocc = g_boc[0] + g_boc[1] + g_boc[2] + g_boc[3];
    int v0 = blockIdx.y << 7;
    if (v0 >= nocc) return;
    extern __shared__ char smem[];
    uint32_t sbase = smem_u32(smem);
    int tid = threadIdx.x;
    int warp = tid >> 5, lane = tid & 31;
    int c0 = blockIdx.x << 7;
    const float* fb = g_fea + (size_t)v0 * C2;
    const float* wb = g_wr + (size_t)c0 * C2;

    int warp_m0 = (warp >> 2) << 6;
    int warp_n0 = (warp & 3) << 5;

    float acc[4][4][4];
    #pragma unroll
    for (int i = 0; i < 4; i++)
        #pragma unroll
        for (int j = 0; j < 4; j++)
            #pragma unroll
            for (int k = 0; k < 4; k++) acc[i][j][k] = 0.f;

    int lr = tid >> 1;
    int lj0 = (tid & 1) * 4;

    auto load_chunk = [&](int c, int s) {
        int k0 = c * 32;
        uint32_t sA = sbase + s * STAGE_BYTES;
        uint32_t sB = sA + 16384;
        const float* ga = wb + (size_t)lr * C2 + k0 + lj0 * 4;
        const float* gb = fb + (size_t)lr * C2 + k0 + lj0 * 4;
        #pragma unroll
        for (int jj = 0; jj < 4; jj++) {
            uint32_t off = SWZ((uint32_t)lr, (uint32_t)((lj0 + jj) * 16));
            cp_async16(sA + off, ga + jj * 4);
            cp_async16(sB + off, gb + jj * 4);
        }
    };

    #pragma unroll
    for (int s = 0; s < GSTAGES; s++) {
        load_chunk(s, s);
        asm volatile("cp.async.commit_group;" ::: "memory");
    }
    asm volatile("cp.async.wait_group 2;" ::: "memory");
    __syncthreads();

    for (int c = 0; c < NCHUNK; c++) {
        int s = c % GSTAGES;
        uint32_t sA = sbase + s * STAGE_BYTES;
        uint32_t sB = sA + 16384;
        #pragma unroll
        for (int ks = 0; ks < 4; ks++) {
            uint32_t a[4][4];
            #pragma unroll
            for (int mi = 0; mi < 4; mi++) {
                uint32_t row = (uint32_t)(warp_m0 + mi * 16 + (lane & 15));
                uint32_t cb = (uint32_t)(ks * 32 + ((lane >> 4) << 4));
                ldsm_x4(a[mi], sA + SWZ(row, cb));
            }
            uint32_t bf[2][4];
            #pragma unroll
            for (int p = 0; p < 2; p++) {
                uint32_t row = (uint32_t)(warp_n0 + p * 16 + (lane & 7) + ((lane >> 4) << 3));
                uint32_t cb = (uint32_t)(ks * 32 + (((lane >> 3) & 1) << 4));
                ldsm_x4(bf[p], sB + SWZ(row, cb));
            }
            #pragma unroll
            for (int mi = 0; mi < 4; mi++)
                #pragma unroll
                for (int nf = 0; nf < 4; nf++)
                    mma_tf32(acc[mi][nf], a[mi], bf[nf >> 1][(nf & 1) * 2],
                             bf[nf >> 1][(nf & 1) * 2 + 1]);
        }
        __syncthreads();
        if (c + GSTAGES < NCHUNK) load_chunk(c + GSTAGES, s);
        asm volatile("cp.async.commit_group;" ::: "memory");
        asm volatile("cp.async.wait_group 2;" ::: "memory");
        __syncthreads();
    }

    // epilogue: store compact yc = acc + bias; BN partials masked to v < nocc
    #pragma unroll
    for (int mi = 0; mi < 4; mi++) {
        int ch0 = c0 + warp_m0 + mi * 16 + (lane >> 2);
        int ch1 = ch0 + 8;
        float bi0 = (ch0 < C) ? bias[ch0] : 0.f;
        float bi1 = (ch1 < C) ? bias[ch1] : 0.f;
        float* y0 = g_yc + (size_t)(ch0 < C ? ch0 : 0) * NOCCMAX;
        float* y1 = g_yc + (size_t)(ch1 < C ? ch1 : 0) * NOCCMAX;
        float s0 = 0.f, q0 = 0.f, s1 = 0.f, q1 = 0.f;
        #pragma unroll
        for (int nf = 0; nf < 4; nf++) {
            int v = v0 + warp_n0 + nf * 8 + (lane & 3) * 2;
            float a0 = acc[mi][nf][0] + bi0, a1 = acc[mi][nf][1] + bi0;
            float a2 = acc[mi][nf][2] + bi1, a3 = acc[mi][nf][3] + bi1;
            if (ch0 < C) *(float2*)(y0 + v) = make_float2(a0, a1);
            if (ch1 < C) *(float2*)(y1 + v) = make_float2(a2, a3);
            bool m0 = v < nocc, m1 = v + 1 < nocc;
            s0 += (m0 ? a0 : 0.f) + (m1 ? a1 : 0.f);
            q0 += (m0 ? a0 * a0 : 0.f) + (m1 ? a1 * a1 : 0.f);
            s1 += (m0 ? a2 : 0.f) + (m1 ? a3 : 0.f);
            q1 += (m0 ? a2 * a2 : 0.f) + (m1 ? a3 * a3 : 0.f);
        }
        #pragma unroll
        for (int o = 1; o <= 2; o <<= 1) {
            s0 += __shfl_xor_sync(0xffffffffu, s0, o);
            q0 += __shfl_xor_sync(0xffffffffu, q0, o);
            s1 += __shfl_xor_sync(0xffffffffu, s1, o);
            q1 += __shfl_xor_sync(0xffffffffu, q1, o);
        }
        if ((lane & 3) == 0) {
            if (ch0 < C) { atomicAdd(&g_sum[ch0], s0); atomicAdd(&g_sum2[ch0], q0); }
            if (ch1 < C) { atomicAdd(&g_sum[ch1], s1); atomicAdd(&g_sum2[ch1], q1); }
        }
    }
}

// ---------------- K8: BN finalize (tiny) ----------------
__global__ void k_bnfin(const float* __restrict__ bias, const float* __restrict__ gamma,
                        const float* __restrict__ beta) {
    int c = threadIdx.x;
    if (c >= C) return;
    int nocc = g_boc[0] + g_boc[1] + g_boc[2] + g_boc[3];
    float bi = bias[c];
    const float invT = 1.0f / (float)(NB * R3);
    float n_e = (float)(NB * R3 - nocc);
    float mean = (g_sum[c] + n_e * bi) * invT;
    float var = (g_sum2[c] + n_e * bi * bi) * invT - mean * mean;
    float A = gamma[c] * rsqrtf(var + BN_EPS);
    g_bnA[c] = A;
    g_bnB[c] = beta[c] - mean * A;
}

// ---------------- K9: expand compact -> dense + BN + swish ----------------
__global__ void __launch_bounds__(256) k_out(float* __restrict__ y,
                                             const float* __restrict__ bias) {
    size_t i4 = (size_t)blockIdx.x * blockDim.x + threadIdx.x;
    const size_t TOT4 = (size_t)NB * C * R3 / 4;
    if (i4 >= TOT4) return;
    size_t idx = i4 * 4;
    int bc = (int)(idx >> 15);
    int c = bc % C;
    int b = bc / C;
    int v = (int)(idx & (R3 - 1));
    int pb = 0;
    #pragma unroll
    for (int j = 0; j < NB; j++) pb += (j < b) ? g_boc[j] : 0;

    float bi = bias[c];
    float A = g_bnA[c], Bv = g_bnB[c];

    int4 g = *(const int4*)(g_gidx + (b << 15) + v);
    const float* yc = g_yc + (size_t)c * NOCCMAX + pb;
    float x0 = (g.x >= 0) ? yc[g.x] : bi;
    float x1 = (g.y >= 0) ? yc[g.y] : bi;
    float x2 = (g.z >= 0) ? yc[g.z] : bi;
    float x3 = (g.w >= 0) ? yc[g.w] : bi;
    x0 = x0 * A + Bv; x1 = x1 * A + Bv; x2 = x2 * A + Bv; x3 = x3 * A + Bv;
    float4 o;
    o.x = x0 / (1.f + __expf(-x0));
    o.y = x1 / (1.f + __expf(-x1));
    o.z = x2 / (1.f + __expf(-x2));
    o.w = x3 / (1.f + __expf(-x3));
    *(float4*)(y + idx) = o;
}

// ---------------- launch ----------------
extern "C" void kernel_launch(void* const* d_in, const int* in_sizes, int n_in,
                              void* d_out, int out_size) {
    const float* features = (const float*)d_in[0];
    const float* coords   = (const float*)d_in[1];
    const float* w        = (const float*)d_in[2];
    const float* bias     = (const float*)d_in[3];
    const float* gamma    = (const float*)d_in[4];
    const float* beta     = (const float*)d_in[5];
    float* out = (float*)d_out;

    const int Y_SIZE = NB * C * R3;
    const int NC_SIZE = NB * 3 * NP;
    int write_nc = (out_size >= Y_SIZE + NC_SIZE) ? 1 : 0;
    float* nc_out = out + Y_SIZE;

    const int GEMM_SMEM = GSTAGES * STAGE_BYTES;   // 96 KB
    static cudaStream_t s1 = nullptr;
    static cudaEvent_t evA = nullptr, evT = nullptr;
    if (!s1) {
        cudaFuncSetAttribute(k_gemm_mma, cudaFuncAttributeMaxDynamicSharedMemorySize,
                             GEMM_SMEM);
        cudaStreamCreateWithFlags(&s1, cudaStreamNonBlocking);
        cudaEventCreateWithFlags(&evA, cudaEventDisableTiming);
        cudaEventCreateWithFlags(&evT, cudaEventDisableTiming);
    }

    // fork: transpose on s1 overlaps the voxel chain
    cudaEventRecord(evA, 0);
    cudaStreamWaitEvent(s1, evA, 0);
    {
        dim3 grd(NP / 128, 8, NB);
        k_transpose<<<grd, 256, 0, s1>>>(features);
    }
    cudaEventRecord(evT, s1);

    // main chain
    k_setup<<<512, 256>>>(w, coords);
    {
        dim3 grd(NP / 4 / 256, NB);
        k_cmax<<<grd, 256>>>(coords);
    }
    k_voxelize<<<(NB * NP + 255) / 256, 256>>>(coords, nc_out, write_nc);
    k_scan<<<NB, 1024>>>();
    k_scatter<<<(NB * NP + 255) / 256, 256>>>();

    // join: gather needs both scatter (main) and transpose (s1)
    cudaStreamWaitEvent(0, evT, 0);
    k_gather<<<(NVOX) / 8, 256>>>();
    {
        dim3 grd(2, NOCCMAX / 128);
        k_gemm_mma<<<grd, 256, GEMM_SMEM>>>(bias);
    }
    k_bnfin<<<1, 256>>>(bias, gamma, beta);
    {
        size_t tot4 = (size_t)NB * C * R3 / 4;
        k_out<<<(unsigned)((tot4 + 255) / 256), 256>>>(out, bias);
    }
}

// round 16
// speedup vs baseline: 1.3258x; 1.0445x over previous
#include <cuda_runtime.h>
#include <math_constants.h>
#include <cstdint>

#define RR 32
#define R3 32768
#define C 240
#define C2 480
#define NB 4
#define NP 32768
#define NVOX (NB * R3)
#define NOCCMAX 131072
#define BN_EPS 1e-5f

// ---------------- static scratch ----------------
__device__ float    g_cpart[128][3];
__device__ float    g_meanv[NB][3];
__device__ unsigned g_qmax[NB];
__device__ int   g_pos[NB * NP];
__device__ int   g_count[NVOX];
__device__ int   g_offset[NVOX];
__device__ int   g_gidx[NVOX];
__device__ int   g_boc[NB];
__device__ int   g_plist[NB * NP];
__device__ float g_ft[(size_t)NB * NP * C];
__device__ float g_fea[(size_t)NVOX * C2];
__device__ float g_yc[(size_t)C * NOCCMAX];
__device__ float g_wr[256 * C2];
__device__ float g_sum[C];
__device__ float g_sum2[C];

// ---------------- helpers ----------------
__device__ __forceinline__ float tf32_rna(float x) {
    uint32_t u; asm("cvt.rna.tf32.f32 %0, %1;" : "=r"(u) : "f"(x));
    return __uint_as_float(u);
}
__device__ __forceinline__ uint32_t smem_u32(const void* p) {
    uint32_t a;
    asm("{ .reg .u64 t; cvta.to.shared.u64 t, %1; cvt.u32.u64 %0, t; }" : "=r"(a) : "l"(p));
    return a;
}
__device__ __forceinline__ void cp_async16(uint32_t dst, const void* src) {
    asm volatile("cp.async.cg.shared.global [%0], [%1], 16;" :: "r"(dst), "l"(src) : "memory");
}
__device__ __forceinline__ void ldsm_x4(uint32_t* r, uint32_t addr) {
    asm volatile("ldmatrix.sync.aligned.m8n8.x4.shared.b16 {%0,%1,%2,%3}, [%4];"
                 : "=r"(r[0]), "=r"(r[1]), "=r"(r[2]), "=r"(r[3]) : "r"(addr));
}
__device__ __forceinline__ void mma_tf32(float* c, const uint32_t* a, uint32_t b0, uint32_t b1) {
    asm volatile("mma.sync.aligned.m16n8k8.row.col.f32.tf32.tf32.f32 "
                 "{%0,%1,%2,%3}, {%4,%5,%6,%7}, {%8,%9}, {%0,%1,%2,%3};"
                 : "+f"(c[0]), "+f"(c[1]), "+f"(c[2]), "+f"(c[3])
                 : "r"(a[0]), "r"(a[1]), "r"(a[2]), "r"(a[3]), "r"(b0), "r"(b1));
}
__device__ __forceinline__ void fmax4(float4& m, const float4& x) {
    m.x = fmaxf(m.x, x.x); m.y = fmaxf(m.y, x.y);
    m.z = fmaxf(m.z, x.z); m.w = fmaxf(m.w, x.w);
}
__device__ __forceinline__ void fmin4(float4& m, const float4& x) {
    m.x = fminf(m.x, x.x); m.y = fminf(m.y, x.y);
    m.z = fminf(m.z, x.z); m.w = fminf(m.w, x.w);
}

// ---------------- K_setup ----------------
__global__ void __launch_bounds__(256) k_setup(const float* __restrict__ w,
                                               const float* __restrict__ coords) {
    int i = blockIdx.x * 256 + threadIdx.x;
    if (i < NVOX) g_count[i] = 0;
    if (i < C) { g_sum[i] = 0.f; g_sum2[i] = 0.f; }
    if (i < NB) g_qmax[i] = 0u;
    if (i < 256 * C2) {
        int r = i / C2;
        g_wr[i] = (r < C) ? tf32_rna(w[i]) : 0.f;
    }
    if (blockIdx.x < 128) {
        int b = blockIdx.x >> 5;
        int idx = (blockIdx.x & 31) * 256 + threadIdx.x;
        const float4* cx = (const float4*)(coords + (size_t)b * 3 * NP);
        float4 a = cx[idx];
        float4 c = cx[NP / 4 + idx];
        float4 d = cx[NP / 2 + idx];
        float sx = (a.x + a.y) + (a.z + a.w);
        float sy = (c.x + c.y) + (c.z + c.w);
        float sz = (d.x + d.y) + (d.z + d.w);
        __shared__ float sh[3][8];
        int lane = threadIdx.x & 31, warp = threadIdx.x >> 5;
        #pragma unroll
        for (int o = 16; o; o >>= 1) {
            sx += __shfl_down_sync(0xffffffffu, sx, o);
            sy += __shfl_down_sync(0xffffffffu, sy, o);
            sz += __shfl_down_sync(0xffffffffu, sz, o);
        }
        if (lane == 0) { sh[0][warp] = sx; sh[1][warp] = sy; sh[2][warp] = sz; }
        __syncthreads();
        if (threadIdx.x == 0) {
            float tx = 0.f, ty = 0.f, tz = 0.f;
            #pragma unroll
            for (int j = 0; j < 8; j++) { tx += sh[0][j]; ty += sh[1][j]; tz += sh[2][j]; }
            g_cpart[blockIdx.x][0] = tx;
            g_cpart[blockIdx.x][1] = ty;
            g_cpart[blockIdx.x][2] = tz;
        }
    }
}

// ---------------- K_cmax ----------------
__global__ void __launch_bounds__(256) k_cmax(const float* __restrict__ coords) {
    int b = blockIdx.y;
    __shared__ float mean_s[3];
    if (threadIdx.x < 3) {
        float s = 0.f;
        #pragma unroll
        for (int j = 0; j < 32; j++) s += g_cpart[(b << 5) + j][threadIdx.x];
        float m = s * (1.0f / (float)NP);
        mean_s[threadIdx.x] = m;
        if (blockIdx.x == 0) g_meanv[b][threadIdx.x] = m;
    }
    __syncthreads();
    float m0 = mean_s[0], m1 = mean_s[1], m2 = mean_s[2];
    int idx = blockIdx.x * blockDim.x + threadIdx.x;
    const float4* cx = (const float4*)(coords + (size_t)b * 3 * NP);
    float4 a = cx[idx];
    float4 c = cx[NP / 4 + idx];
    float4 d = cx[NP / 2 + idx];
    float mx = 0.f, dx, dy, dz, q;
    dx = a.x - m0; dy = c.x - m1; dz = d.x - m2; q = dx*dx + dy*dy + dz*dz; mx = fmaxf(mx, q);
    dx = a.y - m0; dy = c.y - m1; dz = d.y - m2; q = dx*dx + dy*dy + dz*dz; mx = fmaxf(mx, q);
    dx = a.z - m0; dy = c.z - m1; dz = d.z - m2; q = dx*dx + dy*dy + dz*dz; mx = fmaxf(mx, q);
    dx = a.w - m0; dy = c.w - m1; dz = d.w - m2; q = dx*dx + dy*dy + dz*dz; mx = fmaxf(mx, q);
    __shared__ float sh[8];
    int lane = threadIdx.x & 31, warp = threadIdx.x >> 5;
    #pragma unroll
    for (int o = 16; o; o >>= 1) mx = fmaxf(mx, __shfl_down_sync(0xffffffffu, mx, o));
    if (lane == 0) sh[warp] = mx;
    __syncthreads();
    if (threadIdx.x == 0) {
        float t = 0.f;
        #pragma unroll
        for (int j = 0; j < 8; j++) t = fmaxf(t, sh[j]);
        atomicMax(&g_qmax[b], __float_as_uint(t));
    }
}

// ---------------- K2: nc + voxel id + count ----------------
__global__ void __launch_bounds__(256) k_voxelize(const float* __restrict__ coords,
                                                  float* __restrict__ nc_out, int write_nc) {
    int i = blockIdx.x * blockDim.x + threadIdx.x;
    if (i >= NB * NP) return;
    int b = i >> 15, n = i & (NP - 1);
    const float* base = coords + (size_t)b * 3 * NP;
    float sc = sqrtf(__uint_as_float(g_qmax[b])) * 2.0f;
    int vx[3];
    #pragma unroll
    for (int ch = 0; ch < 3; ch++) {
        float x = base[ch * NP + n];
        float u = (x - g_meanv[b][ch]) / sc + 0.5f;
        float t = fminf(fmaxf(u * (float)RR, 0.0f), (float)(RR - 1));
        if (write_nc) nc_out[((size_t)b * 3 + ch) * NP + n] = t;
        vx[ch] = (int)rintf(t);
    }
    int pos = vx[0] + vx[1] * RR + vx[2] * RR * RR;
    g_pos[i] = pos;
    atomicAdd(&g_count[(b << 15) + pos], 1);
}

// ---------------- K3: per-batch dual scan (points + occupancy) ----------------
__global__ void __launch_bounds__(1024) k_scan() {
    int b = blockIdx.x;
    int t = threadIdx.x;
    int base = b * R3 + t * 32;
    int4 v[8];
    const int4* src = (const int4*)(g_count + base);
    #pragma unroll
    for (int j = 0; j < 8; j++) v[j] = src[j];
    unsigned comb = 0;
    #pragma unroll
    for (int j = 0; j < 8; j++) {
        comb += ((unsigned)(v[j].x) << 16) + (v[j].x > 0);
        comb += ((unsigned)(v[j].y) << 16) + (v[j].y > 0);
        comb += ((unsigned)(v[j].z) << 16) + (v[j].z > 0);
        comb += ((unsigned)(v[j].w) << 16) + (v[j].w > 0);
    }
    __shared__ unsigned warp_sums[32];
    int lane = t & 31, warp = t >> 5;
    unsigned inc = comb;
    #pragma unroll
    for (int o = 1; o < 32; o <<= 1) {
        unsigned u = __shfl_up_sync(0xffffffffu, inc, o);
        if (lane >= o) inc += u;
    }
    if (lane == 31) warp_sums[warp] = inc;
    __syncthreads();
    if (warp == 0) {
        unsigned w = warp_sums[lane];
        #pragma unroll
        for (int o = 1; o < 32; o <<= 1) {
            unsigned u = __shfl_up_sync(0xffffffffu, w, o);
            if (lane >= o) w += u;
        }
        warp_sums[lane] = w;
    }
    __syncthreads();
    unsigned excl = inc - comb + (warp ? warp_sums[warp - 1] : 0u);
    int run_pts = (int)(excl >> 16);
    int run_occ = (int)(excl & 0xFFFFu);
    int4* dsto = (int4*)(g_offset + base);
    int4* dstg = (int4*)(g_gidx + base);
    #pragma unroll
    for (int j = 0; j < 8; j++) {
        int4 o, g;
        o.x = run_pts; g.x = (v[j].x > 0) ? run_occ : -1; run_pts += v[j].x; run_occ += (v[j].x > 0);
        o.y = run_pts; g.y = (v[j].y > 0) ? run_occ : -1; run_pts += v[j].y; run_occ += (v[j].y > 0);
        o.z = run_pts; g.z = (v[j].z > 0) ? run_occ : -1; run_pts += v[j].z; run_occ += (v[j].z > 0);
        o.w = run_pts; g.w = (v[j].w > 0) ? run_occ : -1; run_pts += v[j].w; run_occ += (v[j].w > 0);
        dsto[j] = o;
        dstg[j] = g;
    }
    if (t == 1023) g_boc[b] = run_occ;
}

// ---------------- K4: scatter ----------------
__global__ void __launch_bounds__(256) k_scatter() {
    int i = blockIdx.x * blockDim.x + threadIdx.x;
    if (i >= NB * NP) return;
    int b = i >> 15, n = i & (NP - 1);
    int pos = g_pos[i];
    int slot = atomicAdd(&g_offset[(b << 15) + pos], 1);
    g_plist[(b << 15) + slot] = n;
}

// ---------------- K5: transpose [B,C,N] -> [B,N,C], float4 both directions ----------------
__global__ void __launch_bounds__(256) k_transpose(const float* __restrict__ f) {
    __shared__ float tile[32][132];
    int b = blockIdx.z;
    int c0 = blockIdx.y * 32, n0 = blockIdx.x * 128;
    int t = threadIdx.x;
    int cl = t >> 5;
    int nl = (t & 31) * 4;
    #pragma unroll
    for (int j = 0; j < 4; j++) {
        int c = c0 + j * 8 + cl;
        float4 v = make_float4(0.f, 0.f, 0.f, 0.f);
        if (c < C) v = *(const float4*)(f + ((size_t)b * C + c) * NP + n0 + nl);
        *(float4*)&tile[j * 8 + cl][nl] = v;
    }
    __syncthreads();
    int nw = t >> 3;
    int cw = (t & 7) * 4;
    #pragma unroll
    for (int j = 0; j < 4; j++) {
        int n = n0 + j * 32 + nw;
        int c = c0 + cw;
        if (c < C) {
            int nf = j * 32 + nw;
            float4 o;
            o.x = tile[cw + 0][nf];
            o.y = tile[cw + 1][nf];
            o.z = tile[cw + 2][nf];
            o.w = tile[cw + 3][nf];
            *(float4*)(g_ft + ((size_t)b * NP + n) * C + c) = o;
        }
    }
}

// ---------------- K6: gather into COMPACT fea, float4 channels, 2-point unroll ----------------
__global__ void __launch_bounds__(256) k_gather() {
    int gw = (int)((blockIdx.x * (size_t)blockDim.x + threadIdx.x) >> 5);
    if (gw >= NVOX) return;
    int idx = gw;
    int cnt = g_count[idx];
    if (cnt == 0) return;
    int lane = threadIdx.x & 31;
    int b = gw >> 15;
    int pb = 0;
    #pragma unroll
    for (int j = 0; j < NB; j++) pb += (j < b) ? g_boc[j] : 0;
    int gi = g_gidx[idx] + pb;
    int start = g_offset[idx] - cnt;
    const int* plist = g_plist + (b << 15) + start;
    const float* ftb = g_ft + ((size_t)(b << 15)) * C;
    float4* out4 = (float4*)(g_fea + (size_t)gi * C2);
    float4 mx4[2], mn4[2];
    #pragma unroll
    for (int i = 0; i < 2; i++) {
        mx4[i] = make_float4(-CUDART_INF_F, -CUDART_INF_F, -CUDART_INF_F, -CUDART_INF_F);
        mn4[i] = make_float4(CUDART_INF_F, CUDART_INF_F, CUDART_INF_F, CUDART_INF_F);
    }
    int c40 = lane, c41 = 32 + lane;        // c41 < 60 iff lane < 28
    int p = 0;
    for (; p + 2 <= cnt; p += 2) {
        int n0 = plist[p], n1 = plist[p + 1];
        const float4* r0 = (const float4*)(ftb + (size_t)n0 * C);
        const float4* r1 = (const float4*)(ftb + (size_t)n1 * C);
        float4 x00 = r0[c40];
        float4 x10 = r1[c40];
        fmax4(mx4[0], x00); fmin4(mn4[0], x00);
        fmax4(mx4[0], x10); fmin4(mn4[0], x10);
        if (c41 < 60) {
            float4 x01 = r0[c41];
            float4 x11 = r1[c41];
            fmax4(mx4[1], x01); fmin4(mn4[1], x01);
            fmax4(mx4[1], x11); fmin4(mn4[1], x11);
        }
    }
    if (p < cnt) {
        int n0 = plist[p];
        const float4* r0 = (const float4*)(ftb + (size_t)n0 * C);
        float4 x00 = r0[c40];
        fmax4(mx4[0], x00); fmin4(mn4[0], x00);
        if (c41 < 60) {
            float4 x01 = r0[c41];
            fmax4(mx4[1], x01); fmin4(mn4[1], x01);
        }
    }
    #pragma unroll
    for (int i = 0; i < 2; i++) {
        int c4 = i * 32 + lane;
        if (c4 < 60) {
            float4 a, d;
            a.x = tf32_rna(mx4[i].x); a.y = tf32_rna(mx4[i].y);
            a.z = tf32_rna(mx4[i].z); a.w = tf32_rna(mx4[i].w);
            d.x = tf32_rna(mn4[i].x); d.y = tf32_rna(mn4[i].y);
            d.z = tf32_rna(mn4[i].z); d.w = tf32_rna(mn4[i].w);
            out4[c4] = a;
            out4[60 + c4] = d;
        }
    }
}

// ---------------- K7: tf32 mma GEMM over compact columns, BN-stats fused ----------------
#define GSTAGES 3
#define NCHUNK 15
#define STAGE_BYTES 32768
#define SWZ(row, cb) (((row) << 7) + ((cb) ^ (((row) & 7) << 4)))

__global__ void __launch_bounds__(256) k_gemm_mma(const float* __restrict__ bias) {
    int nocc = g_boc[0] + g_boc[1] + g_boc[2] + g_boc[3];
    int v0 = blockIdx.y << 7;
    if (v0 >= nocc) return;
    extern __shared__ char smem[];
    uint32_t sbase = smem_u32(smem);
    int tid = threadIdx.x;
    int warp = tid >> 5, lane = tid & 31;
    int c0 = blockIdx.x << 7;
    const float* fb = g_fea + (size_t)v0 * C2;
    const float* wb = g_wr + (size_t)c0 * C2;

    int warp_m0 = (warp >> 2) << 6;
    int warp_n0 = (warp & 3) << 5;

    float acc[4][4][4];
    #pragma unroll
    for (int i = 0; i < 4; i++)
        #pragma unroll
        for (int j = 0; j < 4; j++)
            #pragma unroll
            for (int k = 0; k < 4; k++) acc[i][j][k] = 0.f;

    int lr = tid >> 1;
    int lj0 = (tid & 1) * 4;

    auto load_chunk = [&](int c, int s) {
        int k0 = c * 32;
        uint32_t sA = sbase + s * STAGE_BYTES;
        uint32_t sB = sA + 16384;
        const float* ga = wb + (size_t)lr * C2 + k0 + lj0 * 4;
        const float* gb = fb + (size_t)lr * C2 + k0 + lj0 * 4;
        #pragma unroll
        for (int jj = 0; jj < 4; jj++) {
            uint32_t off = SWZ((uint32_t)lr, (uint32_t)((lj0 + jj) * 16));
            cp_async16(sA + off, ga + jj * 4);
            cp_async16(sB + off, gb + jj * 4);
        }
    };

    #pragma unroll
    for (int s = 0; s < GSTAGES; s++) {
        load_chunk(s, s);
        asm volatile("cp.async.commit_group;" ::: "memory");
    }
    asm volatile("cp.async.wait_group 2;" ::: "memory");
    __syncthreads();

    for (int c = 0; c < NCHUNK; c++) {
        int s = c % GSTAGES;
        uint32_t sA = sbase + s * STAGE_BYTES;
        uint32_t sB = sA + 16384;
        #pragma unroll
        for (int ks = 0; ks < 4; ks++) {
            uint32_t a[4][4];
            #pragma unroll
            for (int mi = 0; mi < 4; mi++) {
                uint32_t row = (uint32_t)(warp_m0 + mi * 16 + (lane & 15));
                uint32_t cb = (uint32_t)(ks * 32 + ((lane >> 4) << 4));
                ldsm_x4(a[mi], sA + SWZ(row, cb));
            }
            uint32_t bf[2][4];
            #pragma unroll
            for (int p = 0; p < 2; p++) {
                uint32_t row = (uint32_t)(warp_n0 + p * 16 + (lane & 7) + ((lane >> 4) << 3));
                uint32_t cb = (uint32_t)(ks * 32 + (((lane >> 3) & 1) << 4));
                ldsm_x4(bf[p], sB + SWZ(row, cb));
            }
            #pragma unroll
            for (int mi = 0; mi < 4; mi++)
                #pragma unroll
                for (int nf = 0; nf < 4; nf++)
                    mma_tf32(acc[mi][nf], a[mi], bf[nf >> 1][(nf & 1) * 2],
                             bf[nf >> 1][(nf & 1) * 2 + 1]);
        }
        __syncthreads();
        if (c + GSTAGES < NCHUNK) load_chunk(c + GSTAGES, s);
        asm volatile("cp.async.commit_group;" ::: "memory");
        asm volatile("cp.async.wait_group 2;" ::: "memory");
        __syncthreads();
    }

    #pragma unroll
    for (int mi = 0; mi < 4; mi++) {
        int ch0 = c0 + warp_m0 + mi * 16 + (lane >> 2);
        int ch1 = ch0 + 8;
        float bi0 = (ch0 < C) ? bias[ch0] : 0.f;
        float bi1 = (ch1 < C) ? bias[ch1] : 0.f;
        float* y0 = g_yc + (size_t)(ch0 < C ? ch0 : 0) * NOCCMAX;
        float* y1 = g_yc + (size_t)(ch1 < C ? ch1 : 0) * NOCCMAX;
        float s0 = 0.f, q0 = 0.f, s1 = 0.f, q1 = 0.f;
        #pragma unroll
        for (int nf = 0; nf < 4; nf++) {
            int v = v0 + warp_n0 + nf * 8 + (lane & 3) * 2;
            float a0 = acc[mi][nf][0] + bi0, a1 = acc[mi][nf][1] + bi0;
            float a2 = acc[mi][nf][2] + bi1, a3 = acc[mi][nf][3] + bi1;
            if (ch0 < C) *(float2*)(y0 + v) = make_float2(a0, a1);
            if (ch1 < C) *(float2*)(y1 + v) = make_float2(a2, a3);
            bool m0 = v < nocc, m1 = v + 1 < nocc;
            s0 += (m0 ? a0 : 0.f) + (m1 ? a1 : 0.f);
            q0 += (m0 ? a0 * a0 : 0.f) + (m1 ? a1 * a1 : 0.f);
            s1 += (m0 ? a2 : 0.f) + (m1 ? a3 : 0.f);
            q1 += (m0 ? a2 * a2 : 0.f) + (m1 ? a3 * a3 : 0.f);
        }
        #pragma unroll
        for (int o = 1; o <= 2; o <<= 1) {
            s0 += __shfl_xor_sync(0xffffffffu, s0, o);
            q0 += __shfl_xor_sync(0xffffffffu, q0, o);
            s1 += __shfl_xor_sync(0xffffffffu, s1, o);
            q1 += __shfl_xor_sync(0xffffffffu, q1, o);
        }
        if ((lane & 3) == 0) {
            if (ch0 < C) { atomicAdd(&g_sum[ch0], s0); atomicAdd(&g_sum2[ch0], q0); }
            if (ch1 < C) { atomicAdd(&g_sum[ch1], s1); atomicAdd(&g_sum2[ch1], q1); }
        }
    }
}

// ---------------- K9: expand compact -> dense + BN(block-computed) + swish ----------------
// block = 2048 consecutive floats = exactly one (b,c); thread = 8 elements.
__global__ void __launch_bounds__(256) k_out(float* __restrict__ y,
                                             const float* __restrict__ bias,
                                             const float* __restrict__ gamma,
                                             const float* __restrict__ beta) {
    size_t base = (size_t)blockIdx.x * 2048;
    int bc = (int)(base >> 15);
    int c = bc % C;
    int b = bc / C;
    __shared__ float shA, shB, shBi;
    if (threadIdx.x == 0) {
        int nocc = g_boc[0] + g_boc[1] + g_boc[2] + g_boc[3];
        float bi = bias[c];
        const float invT = 1.0f / (float)(NB * R3);
        float n_e = (float)(NB * R3 - nocc);
        float mean = (g_sum[c] + n_e * bi) * invT;
        float var = (g_sum2[c] + n_e * bi * bi) * invT - mean * mean;
        float A = gamma[c] * rsqrtf(var + BN_EPS);
        shA = A; shB = beta[c] - mean * A; shBi = bi;
    }
    int pb = 0;
    #pragma unroll
    for (int j = 0; j < NB; j++) pb += (j < b) ? g_boc[j] : 0;
    __syncthreads();
    float A = shA, Bv = shB, bi = shBi;
    const float* yc = g_yc + (size_t)c * NOCCMAX + pb;
    size_t idx = base + (size_t)threadIdx.x * 8;
    int v = (int)(idx & (R3 - 1));
    int4 g0 = *(const int4*)(g_gidx + (b << 15) + v);
    int4 g1 = *(const int4*)(g_gidx + (b << 15) + v + 4);
    float x[8];
    x[0] = (g0.x >= 0) ? yc[g0.x] : bi;
    x[1] = (g0.y >= 0) ? yc[g0.y] : bi;
    x[2] = (g0.z >= 0) ? yc[g0.z] : bi;
    x[3] = (g0.w >= 0) ? yc[g0.w] : bi;
    x[4] = (g1.x >= 0) ? yc[g1.x] : bi;
    x[5] = (g1.y >= 0) ? yc[g1.y] : bi;
    x[6] = (g1.z >= 0) ? yc[g1.z] : bi;
    x[7] = (g1.w >= 0) ? yc[g1.w] : bi;
    #pragma unroll
    for (int j = 0; j < 8; j++) {
        float t = x[j] * A + Bv;
        x[j] = t / (1.f + __expf(-t));
    }
    *(float4*)(y + idx)     = make_float4(x[0], x[1], x[2], x[3]);
    *(float4*)(y + idx + 4) = make_float4(x[4], x[5], x[6], x[7]);
}

// ---------------- launch ----------------
extern "C" void kernel_launch(void* const* d_in, const int* in_sizes, int n_in,
                              void* d_out, int out_size) {
    const float* features = (const float*)d_in[0];
    const float* coords   = (const float*)d_in[1];
    const float* w        = (const float*)d_in[2];
    const float* bias     = (const float*)d_in[3];
    const float* gamma    = (const float*)d_in[4];
    const float* beta     = (const float*)d_in[5];
    float* out = (float*)d_out;

    const int Y_SIZE = NB * C * R3;
    const int NC_SIZE = NB * 3 * NP;
    int write_nc = (out_size >= Y_SIZE + NC_SIZE) ? 1 : 0;
    float* nc_out = out + Y_SIZE;

    const int GEMM_SMEM = GSTAGES * STAGE_BYTES;   // 96 KB
    static cudaStream_t s1 = nullptr;
    static cudaEvent_t evA = nullptr, evT = nullptr;
    if (!s1) {
        cudaFuncSetAttribute(k_gemm_mma, cudaFuncAttributeMaxDynamicSharedMemorySize,
                             GEMM_SMEM);
        cudaStreamCreateWithFlags(&s1, cudaStreamNonBlocking);
        cudaEventCreateWithFlags(&evA, cudaEventDisableTiming);
        cudaEventCreateWithFlags(&evT, cudaEventDisableTiming);
    }

    // fork: transpose on s1 overlaps the voxel chain
    cudaEventRecord(evA, 0);
    cudaStreamWaitEvent(s1, evA, 0);
    {
        dim3 grd(NP / 128, 8, NB);
        k_transpose<<<grd, 256, 0, s1>>>(features);
    }
    cudaEventRecord(evT, s1);

    // main chain
    k_setup<<<512, 256>>>(w, coords);
    {
        dim3 grd(NP / 4 / 256, NB);
        k_cmax<<<grd, 256>>>(coords);
    }
    k_voxelize<<<(NB * NP + 255) / 256, 256>>>(coords, nc_out, write_nc);
    k_scan<<<NB, 1024>>>();
    k_scatter<<<(NB * NP + 255) / 256, 256>>>();

    // join: gather needs both scatter (main) and transpose (s1)
    cudaStreamWaitEvent(0, evT, 0);
    k_gather<<<(NVOX) / 8, 256>>>();
    {
        dim3 grd(2, NOCCMAX / 128);
        k_gemm_mma<<<grd, 256, GEMM_SMEM>>>(bias);
    }
    {
        unsigned nblk = (unsigned)((size_t)NB * C * R3 / 2048);
        k_out<<<nblk, 256>>>(out, bias, gamma, beta);
    }
}